// round 9
// baseline (speedup 1.0000x reference)
#include <cuda_runtime.h>
#include <cuda_bf16.h>
#include <math.h>
#include <cstdint>

// Problem dims
#define TGT   64
#define SRC   64
#define BATCH 32
#define HID   512
#define ATT   512

// Scratch (no cudaMalloc allowed)
__device__ float g_hpart[TGT * BATCH * ATT];   // [t*BATCH+b][a]
__device__ float g_spart[SRC * BATCH * ATT];   // [s*BATCH+b][a]
__device__ float g_scores[TGT * BATCH * SRC];  // [(t*BATCH+b)*SRC + s]
__device__ float g_A32[2 * TGT * BATCH * HID]; // tf32-rounded [h_t | src]
__device__ float g_B32[2 * HID * ATT];         // tf32-rounded Wa

// ---------------------------------------------------------------------------
// helpers
// ---------------------------------------------------------------------------
__device__ __forceinline__ float to_tf32(float x) {
    uint32_t u;
    asm("cvt.rna.tf32.f32 %0, %1;" : "=r"(u) : "f"(x));
    return __uint_as_float(u);
}
__device__ __forceinline__ float4 to_tf32_4(float4 v) {
    return make_float4(to_tf32(v.x), to_tf32(v.y), to_tf32(v.z), to_tf32(v.w));
}
__device__ __forceinline__ float tanh_fast(float x) {
    float y;
    asm("tanh.approx.f32 %0, %1;" : "=f"(y) : "f"(x));
    return y;
}
__device__ __forceinline__ uint32_t smem_u32(const void* p) {
    uint32_t a;
    asm("{ .reg .u64 t; cvta.to.shared.u64 t, %1; cvt.u32.u64 %0, t; }"
        : "=r"(a) : "l"(p));
    return a;
}
#define CP_ASYNC16(dst, srcp) \
    asm volatile("cp.async.cg.shared.global [%0], [%1], 16;" :: "r"(dst), "l"(srcp))
#define CP_COMMIT() asm volatile("cp.async.commit_group;" ::: "memory")
#define CP_WAIT1()  asm volatile("cp.async.wait_group 1;" ::: "memory")
#define CP_WAIT0()  asm volatile("cp.async.wait_group 0;" ::: "memory")

__device__ __forceinline__ void mma_tf32(float* c, const float* a, const float* b) {
    uint32_t a0 = __float_as_uint(a[0]), a1 = __float_as_uint(a[1]);
    uint32_t a2 = __float_as_uint(a[2]), a3 = __float_as_uint(a[3]);
    uint32_t b0 = __float_as_uint(b[0]), b1 = __float_as_uint(b[1]);
    asm volatile(
        "mma.sync.aligned.m16n8k8.row.col.f32.tf32.tf32.f32 "
        "{%0,%1,%2,%3}, {%4,%5,%6,%7}, {%8,%9}, {%0,%1,%2,%3};"
        : "+f"(c[0]), "+f"(c[1]), "+f"(c[2]), "+f"(c[3])
        : "r"(a0), "r"(a1), "r"(a2), "r"(a3), "r"(b0), "r"(b1));
}

// ---------------------------------------------------------------------------
// Kernel 0: round inputs to tf32 once. g_A32 = tf32([h_t | src]), g_B32 = tf32(Wa)
// ---------------------------------------------------------------------------
#define NA4 (2 * TGT * BATCH * HID / 4)   // 524288
#define NB4 (2 * HID * ATT / 4)           // 131072

__global__ __launch_bounds__(256) void round_inputs(
    const float* __restrict__ h_t,
    const float* __restrict__ src,
    const float* __restrict__ Wa)
{
    const int stride = gridDim.x * blockDim.x;
    for (int i = blockIdx.x * blockDim.x + threadIdx.x; i < NA4 + NB4; i += stride) {
        if (i < NA4 / 2) {
            ((float4*)g_A32)[i] = to_tf32_4(((const float4*)h_t)[i]);
        } else if (i < NA4) {
            ((float4*)g_A32)[i] = to_tf32_4(((const float4*)src)[i - NA4 / 2]);
        } else {
            ((float4*)g_B32)[i - NA4] = to_tf32_4(((const float4*)Wa)[i - NA4]);
        }
    }
}

// ---------------------------------------------------------------------------
// Kernel 1: tf32 mma GEMM, cp.async triple-buffered. (unchanged from R8)
// CTA tile 128(M) x 64(N), K in 16 stages of 32. 256 CTAs, 2 CTAs/SM.
// ---------------------------------------------------------------------------
#define KT     32
#define ARS    36
#define BRS    72
#define STGF   (128 * ARS + KT * BRS)

__global__ __launch_bounds__(256, 2) void gemm_mma(void)
{
    extern __shared__ __align__(16) float sm[];
    const uint32_t smb = smem_u32(sm);

    const int tid  = threadIdx.x;
    const int lane = tid & 31;
    const int wid  = tid >> 5;
    const int g    = lane >> 2;
    const int tg   = lane & 3;

    const int wm = (wid >> 1) * 32;
    const int wn = (wid & 1) * 32;

    const int ntile = blockIdx.x;
    const int mtile = blockIdx.y;
    const int z  = mtile >> 4;
    const int m0 = (mtile & 15) * 128;
    const int n0 = ntile * 64;
    const float* A = g_A32 + z * (TGT * BATCH * HID);
    const float* B = g_B32 + z * (HID * ATT);
    float*       C = (z == 0) ? g_hpart : g_spart;

    auto stage = [&](int s, int bufi) {
        const int kt = s * KT;
        const uint32_t bufA = smb + (uint32_t)(bufi * STGF) * 4u;
        const uint32_t bufB = bufA + 128u * ARS * 4u;
#pragma unroll
        for (int r = 0; r < 4; r++) {
            const int idx = r * 256 + tid;
            const int am  = idx >> 3, ak4 = idx & 7;
            CP_ASYNC16(bufA + (uint32_t)(am * ARS + ak4 * 4) * 4u,
                       A + (m0 + am) * HID + kt + ak4 * 4);
        }
#pragma unroll
        for (int r = 0; r < 2; r++) {
            const int idx = r * 256 + tid;
            const int bk  = idx >> 4, bn4 = idx & 15;
            CP_ASYNC16(bufB + (uint32_t)(bk * BRS + bn4 * 4) * 4u,
                       B + (kt + bk) * ATT + n0 + bn4 * 4);
        }
    };

    float acc[2][4][4];
#pragma unroll
    for (int mi = 0; mi < 2; mi++)
#pragma unroll
        for (int ni = 0; ni < 4; ni++)
#pragma unroll
            for (int j = 0; j < 4; j++) acc[mi][ni][j] = 0.f;

    stage(0, 0); CP_COMMIT();
    stage(1, 1); CP_COMMIT();

    for (int s = 0; s < 16; s++) {
        if (s < 15) CP_WAIT1(); else CP_WAIT0();
        __syncthreads();
        if (s + 2 < 16) { stage(s + 2, (s + 2) % 3); CP_COMMIT(); }

        const float* Ab = sm + (s % 3) * STGF;
        const float* Bb = Ab + 128 * ARS;
#pragma unroll
        for (int ks = 0; ks < 4; ks++) {
            const int k0 = ks * 8;
            float a[2][4];
#pragma unroll
            for (int mi = 0; mi < 2; mi++) {
                const float* ap = Ab + (wm + mi * 16 + g) * ARS + k0 + tg;
                a[mi][0] = ap[0];
                a[mi][1] = ap[8 * ARS];
                a[mi][2] = ap[4];
                a[mi][3] = ap[8 * ARS + 4];
            }
            float b[4][2];
#pragma unroll
            for (int ni = 0; ni < 4; ni++) {
                const float* bp = Bb + (k0 + tg) * BRS + wn + ni * 8 + g;
                b[ni][0] = bp[0];
                b[ni][1] = bp[4 * BRS];
            }
#pragma unroll
            for (int mi = 0; mi < 2; mi++)
#pragma unroll
                for (int ni = 0; ni < 4; ni++)
                    mma_tf32(acc[mi][ni], a[mi], b[ni]);
        }
    }

#pragma unroll
    for (int mi = 0; mi < 2; mi++) {
#pragma unroll
        for (int ni = 0; ni < 4; ni++) {
            const int row = m0 + wm + mi * 16 + g;
            const int col = n0 + wn + ni * 8 + 2 * tg;
            *(float2*)(C + row * ATT + col)       = make_float2(acc[mi][ni][0], acc[mi][ni][1]);
            *(float2*)(C + (row + 8) * ATT + col) = make_float2(acc[mi][ni][2], acc[mi][ni][3]);
        }
    }
}

// ---------------------------------------------------------------------------
// Kernel 2: scores[s,t,b] = sum_a tanh(h_part[t,b,a] + s_part[s,b,a]) * Va[a]
// (unchanged — MUFU.TANH floor)
// ---------------------------------------------------------------------------
#define SSTR 516

__global__ __launch_bounds__(256) void scores_kernel(
    const float* __restrict__ Va)
{
    extern __shared__ float smem[];
    float* hs = smem;                 // 16 * SSTR
    float* ss = smem + 16 * SSTR;     // 16 * SSTR
    float* va = smem + 32 * SSTR;     // 512

    const int b     = blockIdx.z;
    const int t0    = blockIdx.y * 16;
    const int sbase = blockIdx.x * 32;
    const int tid   = threadIdx.x;

    va[tid]       = Va[tid];
    va[tid + 256] = Va[tid + 256];

#pragma unroll
    for (int r = 0; r < 8; r++) {
        int idx  = r * 256 + tid;
        int row  = idx >> 7;
        int col4 = idx & 127;
        float4 v = *(const float4*)(g_hpart + ((t0 + row) * BATCH + b) * ATT + col4 * 4);
        *(float4*)(hs + row * SSTR + col4 * 4) = v;
    }

    const int si = tid & 15;
    const int ti = tid >> 4;

    for (int sc = 0; sc < 32; sc += 16) {
        __syncthreads();
#pragma unroll
        for (int r = 0; r < 8; r++) {
            int idx  = r * 256 + tid;
            int row  = idx >> 7;
            int col4 = idx & 127;
            float4 v = *(const float4*)(g_spart + ((sbase + sc + row) * BATCH + b) * ATT + col4 * 4);
            *(float4*)(ss + row * SSTR + col4 * 4) = v;
        }
        __syncthreads();

        const float* hp = hs + ti * SSTR;
        const float* sp = ss + si * SSTR;
        float acc = 0.f;
#pragma unroll 4
        for (int a = 0; a < 512; a += 4) {
            float4 h4 = *(const float4*)(hp + a);
            float4 s4 = *(const float4*)(sp + a);
            float4 v4 = *(const float4*)(va + a);
            acc = fmaf(tanh_fast(h4.x + s4.x), v4.x, acc);
            acc = fmaf(tanh_fast(h4.y + s4.y), v4.y, acc);
            acc = fmaf(tanh_fast(h4.z + s4.z), v4.z, acc);
            acc = fmaf(tanh_fast(h4.w + s4.w), v4.w, acc);
        }
        const int s = sbase + sc + si;
        const int t = t0 + ti;
        g_scores[(t * BATCH + b) * SRC + s] = acc;
    }
}

// ---------------------------------------------------------------------------
// Kernel 3: fused softmax + tensor-core context, 64-wide h-chunks.
// Grid (8 hc, 32 b) = 256 blocks, 34.8KB smem, 64 regs -> 4 CTAs/SM.
// mma: M=64(t) x N=64(h') x K=64(s); warp tile 16(t) x 32(h').
// ---------------------------------------------------------------------------
#define ASTR 68    // attn smem stride [t][s]
#define CST2 68    // src chunk smem stride [s][h']

__global__ __launch_bounds__(256) void softmax_context_kernel(
    const float* __restrict__ src,
    float* __restrict__ out)
{
    extern __shared__ float dsm[];
    float* at = dsm;                 // attn^T [t][s]: 64*ASTR = 4352 floats
    float* ss = dsm + 64 * ASTR;     // src chunk [s][h']: 64*CST2 = 4352 floats

    const int b   = blockIdx.y;
    const int hc  = blockIdx.x;      // 0..7
    const int h0  = hc * 64;
    const int tid = threadIdx.x;
    const int wid  = tid >> 5;
    const int lane = tid & 31;

    // --- softmax: warp wi handles t = wi*8 .. wi*8+7, writes attn^T tf32 ---
#pragma unroll
    for (int r = 0; r < 8; r++) {
        const int t = wid * 8 + r;
        const float* srow = g_scores + (t * BATCH + b) * SRC;
        float v0 = srow[lane];
        float v1 = srow[lane + 32];
        float mx = fmaxf(v0, v1);
#pragma unroll
        for (int o = 16; o > 0; o >>= 1)
            mx = fmaxf(mx, __shfl_xor_sync(0xffffffffu, mx, o));
        float e0 = __expf(v0 - mx);
        float e1 = __expf(v1 - mx);
        float sum = e0 + e1;
#pragma unroll
        for (int o = 16; o > 0; o >>= 1)
            sum += __shfl_xor_sync(0xffffffffu, sum, o);
        float inv = 1.0f / sum;
        at[t * ASTR + lane]      = to_tf32(e0 * inv);
        at[t * ASTR + lane + 32] = to_tf32(e1 * inv);
    }

    // --- stage src chunk: 64 rows x 64 floats (16 float4/row), tf32-rounded ---
#pragma unroll
    for (int r = 0; r < 4; r++) {
        const int idx = r * 256 + tid;     // 0..1023 float4 slots
        const int s   = idx >> 4;
        const int c4  = idx & 15;
        float4 v = *(const float4*)(src + (s * BATCH + b) * HID + h0 + c4 * 4);
        *(float4*)(ss + s * CST2 + c4 * 4) = to_tf32_4(v);
    }
    __syncthreads();

    // --- mma: warp tile 16(t) x 32(h'), warps 4x2 ---
    const int g  = lane >> 2;
    const int tg = lane & 3;
    const int wm = (wid & 3) * 16;       // t offset
    const int wn = (wid >> 2) * 32;      // h' offset

    float acc[4][4];
#pragma unroll
    for (int ni = 0; ni < 4; ni++)
#pragma unroll
        for (int j = 0; j < 4; j++) acc[ni][j] = 0.f;

#pragma unroll
    for (int ks = 0; ks < 8; ks++) {
        const int k0 = ks * 8;
        float a[4];
        {
            const float* ap = at + (wm + g) * ASTR + k0 + tg;
            a[0] = ap[0];
            a[1] = ap[8 * ASTR];
            a[2] = ap[4];
            a[3] = ap[8 * ASTR + 4];
        }
        float bfr[4][2];
#pragma unroll
        for (int ni = 0; ni < 4; ni++) {
            const float* bp = ss + (k0 + tg) * CST2 + wn + ni * 8 + g;
            bfr[ni][0] = bp[0];
            bfr[ni][1] = bp[4 * CST2];
        }
#pragma unroll
        for (int ni = 0; ni < 4; ni++)
            mma_tf32(acc[ni], a, bfr[ni]);
    }

    // --- writeback ---
#pragma unroll
    for (int ni = 0; ni < 4; ni++) {
        const int t   = wm + g;
        const int col = h0 + wn + ni * 8 + 2 * tg;
        *(float2*)(out + (t * BATCH + b) * HID + col)       = make_float2(acc[ni][0], acc[ni][1]);
        *(float2*)(out + ((t + 8) * BATCH + b) * HID + col) = make_float2(acc[ni][2], acc[ni][3]);
    }
}

// ---------------------------------------------------------------------------
extern "C" void kernel_launch(void* const* d_in, const int* in_sizes, int n_in,
                              void* d_out, int out_size)
{
    const float* h_t  = (const float*)d_in[0];   // (64, 32, 512)
    const float* srce = (const float*)d_in[1];   // (64, 32, 512)
    const float* Wa   = (const float*)d_in[2];   // (1024, 512)
    const float* Va   = (const float*)d_in[3];   // (512,)
    float* out = (float*)d_out;                  // (64, 32, 512)

    (void)in_sizes; (void)n_in; (void)out_size;

    // 0) tf32 pre-round
    round_inputs<<<256, 256>>>(h_t, srce, Wa);

    // 1) GEMMs: grid (8 n, 32 m) = 256 CTAs, 2/SM, cp.async triple buffer
    const int gemm_smem = 3 * STGF * (int)sizeof(float);   // 82944 B
    cudaFuncSetAttribute(gemm_mma,
                         cudaFuncAttributeMaxDynamicSharedMemorySize, gemm_smem);
    gemm_mma<<<dim3(8, 32), 256, gemm_smem>>>();

    // 2) scores: grid (s-halves=2, t-tiles=4, b=32)
    const int sc_smem = (32 * SSTR + 512) * (int)sizeof(float);
    cudaFuncSetAttribute(scores_kernel,
                         cudaFuncAttributeMaxDynamicSharedMemorySize, sc_smem);
    scores_kernel<<<dim3(2, 4, 32), 256, sc_smem>>>(Va);

    // 3) fused softmax + mma context: grid (8 hc, 32 b) = 256 blocks, 4 CTA/SM
    const int ctx_smem = (64 * ASTR + 64 * CST2) * (int)sizeof(float);  // 34816 B
    cudaFuncSetAttribute(softmax_context_kernel,
                         cudaFuncAttributeMaxDynamicSharedMemorySize, ctx_smem);
    softmax_context_kernel<<<dim3(8, 32), 256, ctx_smem>>>(srce, out);
}

// round 10
// speedup vs baseline: 1.0407x; 1.0407x over previous
#include <cuda_runtime.h>
#include <cuda_bf16.h>
#include <math.h>
#include <cstdint>

// Problem dims
#define TGT   64
#define SRC   64
#define BATCH 32
#define HID   512
#define ATT   512

// Scratch (no cudaMalloc allowed)
__device__ float g_hpart[TGT * BATCH * ATT];   // [t*BATCH+b][a]
__device__ float g_spart[SRC * BATCH * ATT];   // [s*BATCH+b][a]
__device__ float g_scores[TGT * BATCH * SRC];  // [(t*BATCH+b)*SRC + s]

// ---------------------------------------------------------------------------
// helpers
// ---------------------------------------------------------------------------
__device__ __forceinline__ float to_tf32(float x) {
    uint32_t u;
    asm("cvt.rna.tf32.f32 %0, %1;" : "=r"(u) : "f"(x));
    return __uint_as_float(u);
}
__device__ __forceinline__ float4 to_tf32_4(float4 v) {
    return make_float4(to_tf32(v.x), to_tf32(v.y), to_tf32(v.z), to_tf32(v.w));
}
__device__ __forceinline__ float tanh_fast(float x) {
    float y;
    asm("tanh.approx.f32 %0, %1;" : "=f"(y) : "f"(x));
    return y;
}
__device__ __forceinline__ uint32_t smem_u32(const void* p) {
    uint32_t a;
    asm("{ .reg .u64 t; cvta.to.shared.u64 t, %1; cvt.u32.u64 %0, t; }"
        : "=r"(a) : "l"(p));
    return a;
}
#define CP_ASYNC16(dst, srcp) \
    asm volatile("cp.async.cg.shared.global [%0], [%1], 16;" :: "r"(dst), "l"(srcp))
#define CP_COMMIT() asm volatile("cp.async.commit_group;" ::: "memory")
#define CP_WAIT1()  asm volatile("cp.async.wait_group 1;" ::: "memory")
#define CP_WAIT0()  asm volatile("cp.async.wait_group 0;" ::: "memory")

__device__ __forceinline__ void mma_tf32(float* c, const float* a, const float* b) {
    uint32_t a0 = __float_as_uint(a[0]), a1 = __float_as_uint(a[1]);
    uint32_t a2 = __float_as_uint(a[2]), a3 = __float_as_uint(a[3]);
    uint32_t b0 = __float_as_uint(b[0]), b1 = __float_as_uint(b[1]);
    asm volatile(
        "mma.sync.aligned.m16n8k8.row.col.f32.tf32.tf32.f32 "
        "{%0,%1,%2,%3}, {%4,%5,%6,%7}, {%8,%9}, {%0,%1,%2,%3};"
        : "+f"(c[0]), "+f"(c[1]), "+f"(c[2]), "+f"(c[3])
        : "r"(a0), "r"(a1), "r"(a2), "r"(a3), "r"(b0), "r"(b1));
}

// ---------------------------------------------------------------------------
// Kernel 1: tf32 mma GEMM, cp.async triple-buffered, tf32 rounding applied
// on fragment load (no pre-round pass).
//   C[m][n] = sum_k A[m][k] * Wa_z[k][n]
// CTA tile 128(M) x 64(N), K in 16 stages of 32. 256 CTAs, 2 CTAs/SM.
// ---------------------------------------------------------------------------
#define KT     32
#define ARS    36
#define BRS    72
#define STGF   (128 * ARS + KT * BRS)

__global__ __launch_bounds__(256, 2) void gemm_mma(
    const float* __restrict__ h_t,
    const float* __restrict__ src,
    const float* __restrict__ Wa)
{
    extern __shared__ __align__(16) float sm[];
    const uint32_t smb = smem_u32(sm);

    const int tid  = threadIdx.x;
    const int lane = tid & 31;
    const int wid  = tid >> 5;
    const int g    = lane >> 2;
    const int tg   = lane & 3;

    const int wm = (wid >> 1) * 32;
    const int wn = (wid & 1) * 32;

    const int ntile = blockIdx.x;
    const int mtile = blockIdx.y;
    const int z  = mtile >> 4;
    const int m0 = (mtile & 15) * 128;
    const int n0 = ntile * 64;
    const float* A = (z == 0) ? h_t : src;
    const float* B = Wa + z * (HID * ATT);       // [k][n]
    float*       C = (z == 0) ? g_hpart : g_spart;

    auto stage = [&](int s, int bufi) {
        const int kt = s * KT;
        const uint32_t bufA = smb + (uint32_t)(bufi * STGF) * 4u;
        const uint32_t bufB = bufA + 128u * ARS * 4u;
#pragma unroll
        for (int r = 0; r < 4; r++) {
            const int idx = r * 256 + tid;
            const int am  = idx >> 3, ak4 = idx & 7;
            CP_ASYNC16(bufA + (uint32_t)(am * ARS + ak4 * 4) * 4u,
                       A + (m0 + am) * HID + kt + ak4 * 4);
        }
#pragma unroll
        for (int r = 0; r < 2; r++) {
            const int idx = r * 256 + tid;
            const int bk  = idx >> 4, bn4 = idx & 15;
            CP_ASYNC16(bufB + (uint32_t)(bk * BRS + bn4 * 4) * 4u,
                       B + (kt + bk) * ATT + n0 + bn4 * 4);
        }
    };

    float acc[2][4][4];
#pragma unroll
    for (int mi = 0; mi < 2; mi++)
#pragma unroll
        for (int ni = 0; ni < 4; ni++)
#pragma unroll
            for (int j = 0; j < 4; j++) acc[mi][ni][j] = 0.f;

    stage(0, 0); CP_COMMIT();
    stage(1, 1); CP_COMMIT();

    for (int s = 0; s < 16; s++) {
        if (s < 15) CP_WAIT1(); else CP_WAIT0();
        __syncthreads();
        if (s + 2 < 16) { stage(s + 2, (s + 2) % 3); CP_COMMIT(); }

        const float* Ab = sm + (s % 3) * STGF;
        const float* Bb = Ab + 128 * ARS;
#pragma unroll
        for (int ks = 0; ks < 4; ks++) {
            const int k0 = ks * 8;
            float a[2][4];
#pragma unroll
            for (int mi = 0; mi < 2; mi++) {
                const float* ap = Ab + (wm + mi * 16 + g) * ARS + k0 + tg;
                a[mi][0] = to_tf32(ap[0]);
                a[mi][1] = to_tf32(ap[8 * ARS]);
                a[mi][2] = to_tf32(ap[4]);
                a[mi][3] = to_tf32(ap[8 * ARS + 4]);
            }
            float b[4][2];
#pragma unroll
            for (int ni = 0; ni < 4; ni++) {
                const float* bp = Bb + (k0 + tg) * BRS + wn + ni * 8 + g;
                b[ni][0] = to_tf32(bp[0]);
                b[ni][1] = to_tf32(bp[4 * BRS]);
            }
#pragma unroll
            for (int mi = 0; mi < 2; mi++)
#pragma unroll
                for (int ni = 0; ni < 4; ni++)
                    mma_tf32(acc[mi][ni], a[mi], b[ni]);
        }
    }

#pragma unroll
    for (int mi = 0; mi < 2; mi++) {
#pragma unroll
        for (int ni = 0; ni < 4; ni++) {
            const int row = m0 + wm + mi * 16 + g;
            const int col = n0 + wn + ni * 8 + 2 * tg;
            *(float2*)(C + row * ATT + col)       = make_float2(acc[mi][ni][0], acc[mi][ni][1]);
            *(float2*)(C + (row + 8) * ATT + col) = make_float2(acc[mi][ni][2], acc[mi][ni][3]);
        }
    }
}

// ---------------------------------------------------------------------------
// Kernel 2: scores[s,t,b] = sum_a tanh(h_part[t,b,a] + s_part[s,b,a]) * Va[a]
// (unchanged — MUFU.TANH floor)
// ---------------------------------------------------------------------------
#define SSTR 516

__global__ __launch_bounds__(256) void scores_kernel(
    const float* __restrict__ Va)
{
    extern __shared__ float smem[];
    float* hs = smem;                 // 16 * SSTR
    float* ss = smem + 16 * SSTR;     // 16 * SSTR
    float* va = smem + 32 * SSTR;     // 512

    const int b     = blockIdx.z;
    const int t0    = blockIdx.y * 16;
    const int sbase = blockIdx.x * 32;
    const int tid   = threadIdx.x;

    va[tid]       = Va[tid];
    va[tid + 256] = Va[tid + 256];

#pragma unroll
    for (int r = 0; r < 8; r++) {
        int idx  = r * 256 + tid;
        int row  = idx >> 7;
        int col4 = idx & 127;
        float4 v = *(const float4*)(g_hpart + ((t0 + row) * BATCH + b) * ATT + col4 * 4);
        *(float4*)(hs + row * SSTR + col4 * 4) = v;
    }

    const int si = tid & 15;
    const int ti = tid >> 4;

    for (int sc = 0; sc < 32; sc += 16) {
        __syncthreads();
#pragma unroll
        for (int r = 0; r < 8; r++) {
            int idx  = r * 256 + tid;
            int row  = idx >> 7;
            int col4 = idx & 127;
            float4 v = *(const float4*)(g_spart + ((sbase + sc + row) * BATCH + b) * ATT + col4 * 4);
            *(float4*)(ss + row * SSTR + col4 * 4) = v;
        }
        __syncthreads();

        const float* hp = hs + ti * SSTR;
        const float* sp = ss + si * SSTR;
        float acc = 0.f;
#pragma unroll 4
        for (int a = 0; a < 512; a += 4) {
            float4 h4 = *(const float4*)(hp + a);
            float4 s4 = *(const float4*)(sp + a);
            float4 v4 = *(const float4*)(va + a);
            acc = fmaf(tanh_fast(h4.x + s4.x), v4.x, acc);
            acc = fmaf(tanh_fast(h4.y + s4.y), v4.y, acc);
            acc = fmaf(tanh_fast(h4.z + s4.z), v4.z, acc);
            acc = fmaf(tanh_fast(h4.w + s4.w), v4.w, acc);
        }
        const int s = sbase + sc + si;
        const int t = t0 + ti;
        g_scores[(t * BATCH + b) * SRC + s] = acc;
    }
}

// ---------------------------------------------------------------------------
// Kernel 3: fused softmax + tensor-core context (R8 version, 128-wide hc).
// ---------------------------------------------------------------------------
#define ASTR 68
#define CSTR 132

__global__ __launch_bounds__(256) void softmax_context_kernel(
    const float* __restrict__ src,
    float* __restrict__ out)
{
    extern __shared__ float dsm[];
    float* at = dsm;                 // attn^T [t][s]: 64*ASTR
    float* ss = dsm + 64 * ASTR;     // src chunk [s][h']: 64*CSTR

    const int b   = blockIdx.y;
    const int hc  = blockIdx.x;
    const int h0  = hc * 128;
    const int tid = threadIdx.x;
    const int wid  = tid >> 5;
    const int lane = tid & 31;

#pragma unroll
    for (int r = 0; r < 8; r++) {
        const int t = wid * 8 + r;
        const float* srow = g_scores + (t * BATCH + b) * SRC;
        float v0 = srow[lane];
        float v1 = srow[lane + 32];
        float mx = fmaxf(v0, v1);
#pragma unroll
        for (int o = 16; o > 0; o >>= 1)
            mx = fmaxf(mx, __shfl_xor_sync(0xffffffffu, mx, o));
        float e0 = __expf(v0 - mx);
        float e1 = __expf(v1 - mx);
        float sum = e0 + e1;
#pragma unroll
        for (int o = 16; o > 0; o >>= 1)
            sum += __shfl_xor_sync(0xffffffffu, sum, o);
        float inv = 1.0f / sum;
        at[t * ASTR + lane]      = to_tf32(e0 * inv);
        at[t * ASTR + lane + 32] = to_tf32(e1 * inv);
    }

#pragma unroll
    for (int r = 0; r < 8; r++) {
        const int idx = r * 256 + tid;
        const int s   = idx >> 5;
        const int c4  = idx & 31;
        float4 v = *(const float4*)(src + (s * BATCH + b) * HID + h0 + c4 * 4);
        *(float4*)(ss + s * CSTR + c4 * 4) = to_tf32_4(v);
    }
    __syncthreads();

    const int g  = lane >> 2;
    const int tg = lane & 3;
    const int wm = (wid & 3) * 16;
    const int wn = (wid >> 2) * 64;

    float acc[8][4];
#pragma unroll
    for (int ni = 0; ni < 8; ni++)
#pragma unroll
        for (int j = 0; j < 4; j++) acc[ni][j] = 0.f;

#pragma unroll
    for (int ks = 0; ks < 8; ks++) {
        const int k0 = ks * 8;
        float a[4];
        {
            const float* ap = at + (wm + g) * ASTR + k0 + tg;
            a[0] = ap[0];
            a[1] = ap[8 * ASTR];
            a[2] = ap[4];
            a[3] = ap[8 * ASTR + 4];
        }
        float bfr[8][2];
#pragma unroll
        for (int ni = 0; ni < 8; ni++) {
            const float* bp = ss + (k0 + tg) * CSTR + wn + ni * 8 + g;
            bfr[ni][0] = bp[0];
            bfr[ni][1] = bp[4 * CSTR];
        }
#pragma unroll
        for (int ni = 0; ni < 8; ni++)
            mma_tf32(acc[ni], a, bfr[ni]);
    }

#pragma unroll
    for (int ni = 0; ni < 8; ni++) {
        const int t   = wm + g;
        const int col = h0 + wn + ni * 8 + 2 * tg;
        *(float2*)(out + (t * BATCH + b) * HID + col)       = make_float2(acc[ni][0], acc[ni][1]);
        *(float2*)(out + ((t + 8) * BATCH + b) * HID + col) = make_float2(acc[ni][2], acc[ni][3]);
    }
}

// ---------------------------------------------------------------------------
extern "C" void kernel_launch(void* const* d_in, const int* in_sizes, int n_in,
                              void* d_out, int out_size)
{
    const float* h_t  = (const float*)d_in[0];   // (64, 32, 512)
    const float* srce = (const float*)d_in[1];   // (64, 32, 512)
    const float* Wa   = (const float*)d_in[2];   // (1024, 512)
    const float* Va   = (const float*)d_in[3];   // (512,)
    float* out = (float*)d_out;                  // (64, 32, 512)

    (void)in_sizes; (void)n_in; (void)out_size;

    // 1) GEMMs straight from inputs: grid (8 n, 32 m) = 256 CTAs, 2/SM
    const int gemm_smem = 3 * STGF * (int)sizeof(float);   // 82944 B
    cudaFuncSetAttribute(gemm_mma,
                         cudaFuncAttributeMaxDynamicSharedMemorySize, gemm_smem);
    gemm_mma<<<dim3(8, 32), 256, gemm_smem>>>(h_t, srce, Wa);

    // 2) scores: grid (s-halves=2, t-tiles=4, b=32)
    const int sc_smem = (32 * SSTR + 512) * (int)sizeof(float);
    cudaFuncSetAttribute(scores_kernel,
                         cudaFuncAttributeMaxDynamicSharedMemorySize, sc_smem);
    scores_kernel<<<dim3(2, 4, 32), 256, sc_smem>>>(Va);

    // 3) fused softmax + mma context: grid (4 hc, 32 b) = 128 blocks
    const int ctx_smem = (64 * ASTR + 64 * CSTR) * (int)sizeof(float);
    cudaFuncSetAttribute(softmax_context_kernel,
                         cudaFuncAttributeMaxDynamicSharedMemorySize, ctx_smem);
    softmax_context_kernel<<<dim3(4, 32), 256, ctx_smem>>>(srce, out);
}

// round 11
// speedup vs baseline: 1.0546x; 1.0134x over previous
#include <cuda_runtime.h>
#include <cuda_bf16.h>
#include <math.h>
#include <cstdint>

// Problem dims
#define TGT   64
#define SRC   64
#define BATCH 32
#define HID   512
#define ATT   512

// Scratch (no cudaMalloc allowed)
__device__ float g_hpart[TGT * BATCH * ATT];   // [t*BATCH+b][a]
__device__ float g_spart[SRC * BATCH * ATT];   // [s*BATCH+b][a]
__device__ float g_scores[TGT * BATCH * SRC];  // normalized tf32 attn

// ---------------------------------------------------------------------------
// helpers
// ---------------------------------------------------------------------------
__device__ __forceinline__ float to_tf32(float x) {
    uint32_t u;
    asm("cvt.rna.tf32.f32 %0, %1;" : "=r"(u) : "f"(x));
    return __uint_as_float(u);
}
__device__ __forceinline__ float4 to_tf32_4(float4 v) {
    return make_float4(to_tf32(v.x), to_tf32(v.y), to_tf32(v.z), to_tf32(v.w));
}
__device__ __forceinline__ float tanh_fast(float x) {
    float y;
    asm("tanh.approx.f32 %0, %1;" : "=f"(y) : "f"(x));
    return y;
}
__device__ __forceinline__ uint32_t smem_u32(const void* p) {
    uint32_t a;
    asm("{ .reg .u64 t; cvta.to.shared.u64 t, %1; cvt.u32.u64 %0, t; }"
        : "=r"(a) : "l"(p));
    return a;
}
#define CP_ASYNC16(dst, srcp) \
    asm volatile("cp.async.cg.shared.global [%0], [%1], 16;" :: "r"(dst), "l"(srcp))
#define CP_COMMIT() asm volatile("cp.async.commit_group;" ::: "memory")
#define CP_WAIT1()  asm volatile("cp.async.wait_group 1;" ::: "memory")
#define CP_WAIT0()  asm volatile("cp.async.wait_group 0;" ::: "memory")

__device__ __forceinline__ void mma_tf32(float* c, const float* a, const float* b) {
    uint32_t a0 = __float_as_uint(a[0]), a1 = __float_as_uint(a[1]);
    uint32_t a2 = __float_as_uint(a[2]), a3 = __float_as_uint(a[3]);
    uint32_t b0 = __float_as_uint(b[0]), b1 = __float_as_uint(b[1]);
    asm volatile(
        "mma.sync.aligned.m16n8k8.row.col.f32.tf32.tf32.f32 "
        "{%0,%1,%2,%3}, {%4,%5,%6,%7}, {%8,%9}, {%0,%1,%2,%3};"
        : "+f"(c[0]), "+f"(c[1]), "+f"(c[2]), "+f"(c[3])
        : "r"(a0), "r"(a1), "r"(a2), "r"(a3), "r"(b0), "r"(b1));
}

// ---------------------------------------------------------------------------
// Kernel 1: tf32 mma GEMM, cp.async triple-buffered, fragment-time rounding.
// (unchanged from R10 — measured best)
// ---------------------------------------------------------------------------
#define KT     32
#define ARS    36
#define BRS    72
#define STGF   (128 * ARS + KT * BRS)

__global__ __launch_bounds__(256, 2) void gemm_mma(
    const float* __restrict__ h_t,
    const float* __restrict__ src,
    const float* __restrict__ Wa)
{
    extern __shared__ __align__(16) float sm[];
    const uint32_t smb = smem_u32(sm);

    const int tid  = threadIdx.x;
    const int lane = tid & 31;
    const int wid  = tid >> 5;
    const int g    = lane >> 2;
    const int tg   = lane & 3;

    const int wm = (wid >> 1) * 32;
    const int wn = (wid & 1) * 32;

    const int ntile = blockIdx.x;
    const int mtile = blockIdx.y;
    const int z  = mtile >> 4;
    const int m0 = (mtile & 15) * 128;
    const int n0 = ntile * 64;
    const float* A = (z == 0) ? h_t : src;
    const float* B = Wa + z * (HID * ATT);
    float*       C = (z == 0) ? g_hpart : g_spart;

    auto stage = [&](int s, int bufi) {
        const int kt = s * KT;
        const uint32_t bufA = smb + (uint32_t)(bufi * STGF) * 4u;
        const uint32_t bufB = bufA + 128u * ARS * 4u;
#pragma unroll
        for (int r = 0; r < 4; r++) {
            const int idx = r * 256 + tid;
            const int am  = idx >> 3, ak4 = idx & 7;
            CP_ASYNC16(bufA + (uint32_t)(am * ARS + ak4 * 4) * 4u,
                       A + (m0 + am) * HID + kt + ak4 * 4);
        }
#pragma unroll
        for (int r = 0; r < 2; r++) {
            const int idx = r * 256 + tid;
            const int bk  = idx >> 4, bn4 = idx & 15;
            CP_ASYNC16(bufB + (uint32_t)(bk * BRS + bn4 * 4) * 4u,
                       B + (kt + bk) * ATT + n0 + bn4 * 4);
        }
    };

    float acc[2][4][4];
#pragma unroll
    for (int mi = 0; mi < 2; mi++)
#pragma unroll
        for (int ni = 0; ni < 4; ni++)
#pragma unroll
            for (int j = 0; j < 4; j++) acc[mi][ni][j] = 0.f;

    stage(0, 0); CP_COMMIT();
    stage(1, 1); CP_COMMIT();

    for (int s = 0; s < 16; s++) {
        if (s < 15) CP_WAIT1(); else CP_WAIT0();
        __syncthreads();
        if (s + 2 < 16) { stage(s + 2, (s + 2) % 3); CP_COMMIT(); }

        const float* Ab = sm + (s % 3) * STGF;
        const float* Bb = Ab + 128 * ARS;
#pragma unroll
        for (int ks = 0; ks < 4; ks++) {
            const int k0 = ks * 8;
            float a[2][4];
#pragma unroll
            for (int mi = 0; mi < 2; mi++) {
                const float* ap = Ab + (wm + mi * 16 + g) * ARS + k0 + tg;
                a[mi][0] = to_tf32(ap[0]);
                a[mi][1] = to_tf32(ap[8 * ARS]);
                a[mi][2] = to_tf32(ap[4]);
                a[mi][3] = to_tf32(ap[8 * ARS + 4]);
            }
            float b[4][2];
#pragma unroll
            for (int ni = 0; ni < 4; ni++) {
                const float* bp = Bb + (k0 + tg) * BRS + wn + ni * 8 + g;
                b[ni][0] = to_tf32(bp[0]);
                b[ni][1] = to_tf32(bp[4 * BRS]);
            }
#pragma unroll
            for (int mi = 0; mi < 2; mi++)
#pragma unroll
                for (int ni = 0; ni < 4; ni++)
                    mma_tf32(acc[mi][ni], a[mi], b[ni]);
        }
    }

#pragma unroll
    for (int mi = 0; mi < 2; mi++) {
#pragma unroll
        for (int ni = 0; ni < 4; ni++) {
            const int row = m0 + wm + mi * 16 + g;
            const int col = n0 + wn + ni * 8 + 2 * tg;
            *(float2*)(C + row * ATT + col)       = make_float2(acc[mi][ni][0], acc[mi][ni][1]);
            *(float2*)(C + (row + 8) * ATT + col) = make_float2(acc[mi][ni][2], acc[mi][ni][3]);
        }
    }
}

// ---------------------------------------------------------------------------
// Kernel 2: fused scores + softmax.
// Grid (8 t-tiles, 32 b) = 256 blocks. Block owns 8 t's x all 64 s.
// Warp ti: 32 lanes = (sl 0..15) x (sh = a-half). s staged in 4 chunks of 16.
// Halves combined via shfl_xor(16); in-warp softmax; writes normalized tf32
// attn to g_scores.
// ---------------------------------------------------------------------------
#define SSTR 516

__global__ __launch_bounds__(256) void scores_softmax_kernel(
    const float* __restrict__ Va)
{
    extern __shared__ float smem[];
    float* hs = smem;                 // 8  * SSTR
    float* ss = smem + 8 * SSTR;      // 16 * SSTR
    float* va = smem + 24 * SSTR;     // 512

    const int b   = blockIdx.y;
    const int t0  = blockIdx.x * 8;
    const int tid = threadIdx.x;

    const int ti   = tid >> 5;        // warp -> t = t0 + ti
    const int si   = tid & 31;
    const int sh   = si >> 4;         // a-half
    const int sl   = si & 15;         // s within chunk
    const int aoff = sh * 256;

    va[tid]       = Va[tid];
    va[tid + 256] = Va[tid + 256];

    // stage 8 h rows (1024 float4, 4/thread)
#pragma unroll
    for (int r = 0; r < 4; r++) {
        int idx  = r * 256 + tid;
        int row  = idx >> 7;          // 0..7
        int col4 = idx & 127;
        float4 v = *(const float4*)(g_hpart + ((t0 + row) * BATCH + b) * ATT + col4 * 4);
        *(float4*)(hs + row * SSTR + col4 * 4) = v;
    }

    float sc[4];

#pragma unroll
    for (int c = 0; c < 4; c++) {
        __syncthreads();   // hs staged (c=0) / prior chunk consumed
        // stage 16 s rows (2048 float4, 8/thread)
#pragma unroll
        for (int r = 0; r < 8; r++) {
            int idx  = r * 256 + tid;
            int row  = idx >> 7;      // 0..15
            int col4 = idx & 127;
            float4 v = *(const float4*)(g_spart + ((c * 16 + row) * BATCH + b) * ATT + col4 * 4);
            *(float4*)(ss + row * SSTR + col4 * 4) = v;
        }
        __syncthreads();

        const float* hp = hs + ti * SSTR + aoff;
        const float* sp = ss + sl * SSTR + aoff;
        const float* vp = va + aoff;
        float acc = 0.f;
#pragma unroll 4
        for (int a = 0; a < 256; a += 4) {
            float4 h4 = *(const float4*)(hp + a);
            float4 s4 = *(const float4*)(sp + a);
            float4 v4 = *(const float4*)(vp + a);
            acc = fmaf(tanh_fast(h4.x + s4.x), v4.x, acc);
            acc = fmaf(tanh_fast(h4.y + s4.y), v4.y, acc);
            acc = fmaf(tanh_fast(h4.z + s4.z), v4.z, acc);
            acc = fmaf(tanh_fast(h4.w + s4.w), v4.w, acc);
        }
        sc[c] = acc;
    }

    // combine a-halves (lanes differ in bit 4)
#pragma unroll
    for (int c = 0; c < 4; c++)
        sc[c] += __shfl_xor_sync(0xffffffffu, sc[c], 16);

    // in-warp softmax over 64 s (4 chunks x 16 lanes; both halves identical)
    float mx = fmaxf(fmaxf(sc[0], sc[1]), fmaxf(sc[2], sc[3]));
#pragma unroll
    for (int o = 1; o <= 8; o <<= 1)
        mx = fmaxf(mx, __shfl_xor_sync(0xffffffffu, mx, o));

    float e[4], sum = 0.f;
#pragma unroll
    for (int c = 0; c < 4; c++) { e[c] = __expf(sc[c] - mx); sum += e[c]; }
#pragma unroll
    for (int o = 1; o <= 8; o <<= 1)
        sum += __shfl_xor_sync(0xffffffffu, sum, o);

    const float inv = 1.0f / sum;
    if (sh == 0) {
        float* dst = g_scores + ((t0 + ti) * BATCH + b) * SRC;
#pragma unroll
        for (int c = 0; c < 4; c++)
            dst[c * 16 + sl] = to_tf32(e[c] * inv);
    }
}

// ---------------------------------------------------------------------------
// Kernel 3: lean tensor-core context. attn is pre-normalized tf32 in g_scores.
// Grid (8 hc, 32 b) = 256 blocks, 34.8KB smem -> 4-6 CTAs/SM.
// mma: M=64(t) x N=64(h') x K=64(s); warp tile 16(t) x 32(h').
// ---------------------------------------------------------------------------
#define ASTR 68
#define CST2 68

__global__ __launch_bounds__(256) void context_kernel(
    const float* __restrict__ src,
    float* __restrict__ out)
{
    extern __shared__ float dsm[];
    float* at = dsm;                 // attn [t][s]: 64*ASTR
    float* ss = dsm + 64 * ASTR;     // src chunk [s][h']: 64*CST2

    const int b   = blockIdx.y;
    const int hc  = blockIdx.x;      // 0..7
    const int h0  = hc * 64;
    const int tid = threadIdx.x;
    const int wid  = tid >> 5;
    const int lane = tid & 31;

    // stage attn: 64 rows x 16 float4 (already tf32)
#pragma unroll
    for (int r = 0; r < 4; r++) {
        const int idx = r * 256 + tid;     // 0..1023
        const int t   = idx >> 4;
        const int c4  = idx & 15;
        float4 v = *(const float4*)(g_scores + (t * BATCH + b) * SRC + c4 * 4);
        *(float4*)(at + t * ASTR + c4 * 4) = v;
    }
    // stage src chunk: 64 rows x 16 float4, tf32-rounded
#pragma unroll
    for (int r = 0; r < 4; r++) {
        const int idx = r * 256 + tid;
        const int s   = idx >> 4;
        const int c4  = idx & 15;
        float4 v = *(const float4*)(src + (s * BATCH + b) * HID + h0 + c4 * 4);
        *(float4*)(ss + s * CST2 + c4 * 4) = to_tf32_4(v);
    }
    __syncthreads();

    // mma: warp tile 16(t) x 32(h'), warps 4x2
    const int g  = lane >> 2;
    const int tg = lane & 3;
    const int wm = (wid & 3) * 16;
    const int wn = (wid >> 2) * 32;

    float acc[4][4];
#pragma unroll
    for (int ni = 0; ni < 4; ni++)
#pragma unroll
        for (int j = 0; j < 4; j++) acc[ni][j] = 0.f;

#pragma unroll
    for (int ks = 0; ks < 8; ks++) {
        const int k0 = ks * 8;
        float a[4];
        {
            const float* ap = at + (wm + g) * ASTR + k0 + tg;
            a[0] = ap[0];
            a[1] = ap[8 * ASTR];
            a[2] = ap[4];
            a[3] = ap[8 * ASTR + 4];
        }
        float bfr[4][2];
#pragma unroll
        for (int ni = 0; ni < 4; ni++) {
            const float* bp = ss + (k0 + tg) * CST2 + wn + ni * 8 + g;
            bfr[ni][0] = bp[0];
            bfr[ni][1] = bp[4 * CST2];
        }
#pragma unroll
        for (int ni = 0; ni < 4; ni++)
            mma_tf32(acc[ni], a, bfr[ni]);
    }

#pragma unroll
    for (int ni = 0; ni < 4; ni++) {
        const int t   = wm + g;
        const int col = h0 + wn + ni * 8 + 2 * tg;
        *(float2*)(out + (t * BATCH + b) * HID + col)       = make_float2(acc[ni][0], acc[ni][1]);
        *(float2*)(out + ((t + 8) * BATCH + b) * HID + col) = make_float2(acc[ni][2], acc[ni][3]);
    }
}

// ---------------------------------------------------------------------------
extern "C" void kernel_launch(void* const* d_in, const int* in_sizes, int n_in,
                              void* d_out, int out_size)
{
    const float* h_t  = (const float*)d_in[0];   // (64, 32, 512)
    const float* srce = (const float*)d_in[1];   // (64, 32, 512)
    const float* Wa   = (const float*)d_in[2];   // (1024, 512)
    const float* Va   = (const float*)d_in[3];   // (512,)
    float* out = (float*)d_out;                  // (64, 32, 512)

    (void)in_sizes; (void)n_in; (void)out_size;

    // 1) GEMMs: grid (8 n, 32 m) = 256 CTAs, 2/SM
    const int gemm_smem = 3 * STGF * (int)sizeof(float);   // 82944 B
    cudaFuncSetAttribute(gemm_mma,
                         cudaFuncAttributeMaxDynamicSharedMemorySize, gemm_smem);
    gemm_mma<<<dim3(8, 32), 256, gemm_smem>>>(h_t, srce, Wa);

    // 2) fused scores + softmax: grid (8 t-tiles, 32 b) = 256 blocks
    const int sc_smem = (24 * SSTR + 512) * (int)sizeof(float);   // 51584 B
    cudaFuncSetAttribute(scores_softmax_kernel,
                         cudaFuncAttributeMaxDynamicSharedMemorySize, sc_smem);
    scores_softmax_kernel<<<dim3(8, 32), 256, sc_smem>>>(Va);

    // 3) lean mma context: grid (8 hc, 32 b) = 256 blocks
    const int ctx_smem = (64 * ASTR + 64 * CST2) * (int)sizeof(float);  // 34816 B
    cudaFuncSetAttribute(context_kernel,
                         cudaFuncAttributeMaxDynamicSharedMemorySize, ctx_smem);
    context_kernel<<<dim3(8, 32), 256, ctx_smem>>>(srce, out);
}

// round 12
// speedup vs baseline: 1.2132x; 1.1504x over previous
#include <cuda_runtime.h>
#include <cuda_bf16.h>
#include <cuda_fp16.h>
#include <math.h>
#include <cstdint>

// Problem dims
#define TGT   64
#define SRC   64
#define BATCH 32
#define HID   512
#define ATT   512

// Scratch (no cudaMalloc allowed)
__device__ float g_hpart[TGT * BATCH * ATT];   // [t*BATCH+b][a]
__device__ float g_spart[SRC * BATCH * ATT];   // [s*BATCH+b][a]
__device__ float g_scores[TGT * BATCH * SRC];  // normalized tf32 attn
__device__ __align__(16) __half g_Ah[2 * TGT * BATCH * HID]; // fp16 [h_t|src]
__device__ __align__(16) __half g_Bh[2 * HID * ATT];         // fp16 Wa^T: [z][n][k]

// ---------------------------------------------------------------------------
// helpers
// ---------------------------------------------------------------------------
__device__ __forceinline__ float to_tf32(float x) {
    uint32_t u;
    asm("cvt.rna.tf32.f32 %0, %1;" : "=r"(u) : "f"(x));
    return __uint_as_float(u);
}
__device__ __forceinline__ float4 to_tf32_4(float4 v) {
    return make_float4(to_tf32(v.x), to_tf32(v.y), to_tf32(v.z), to_tf32(v.w));
}
__device__ __forceinline__ float tanh_fast(float x) {
    float y;
    asm("tanh.approx.f32 %0, %1;" : "=f"(y) : "f"(x));
    return y;
}
__device__ __forceinline__ uint32_t smem_u32(const void* p) {
    uint32_t a;
    asm("{ .reg .u64 t; cvta.to.shared.u64 t, %1; cvt.u32.u64 %0, t; }"
        : "=r"(a) : "l"(p));
    return a;
}
#define CP_ASYNC16(dst, srcp) \
    asm volatile("cp.async.cg.shared.global [%0], [%1], 16;" :: "r"(dst), "l"(srcp))
#define CP_COMMIT() asm volatile("cp.async.commit_group;" ::: "memory")
#define CP_WAIT1()  asm volatile("cp.async.wait_group 1;" ::: "memory")
#define CP_WAIT0()  asm volatile("cp.async.wait_group 0;" ::: "memory")

// fp16 mma: D(f32) += A(f16) * B(f16), m16n8k16
__device__ __forceinline__ void mma_f16(float* c, const uint32_t* a, const uint32_t* b) {
    asm volatile(
        "mma.sync.aligned.m16n8k16.row.col.f32.f16.f16.f32 "
        "{%0,%1,%2,%3}, {%4,%5,%6,%7}, {%8,%9}, {%0,%1,%2,%3};"
        : "+f"(c[0]), "+f"(c[1]), "+f"(c[2]), "+f"(c[3])
        : "r"(a[0]), "r"(a[1]), "r"(a[2]), "r"(a[3]), "r"(b[0]), "r"(b[1]));
}

// tf32 mma (context kernel)
__device__ __forceinline__ void mma_tf32(float* c, const float* a, const float* b) {
    uint32_t a0 = __float_as_uint(a[0]), a1 = __float_as_uint(a[1]);
    uint32_t a2 = __float_as_uint(a[2]), a3 = __float_as_uint(a[3]);
    uint32_t b0 = __float_as_uint(b[0]), b1 = __float_as_uint(b[1]);
    asm volatile(
        "mma.sync.aligned.m16n8k8.row.col.f32.tf32.tf32.f32 "
        "{%0,%1,%2,%3}, {%4,%5,%6,%7}, {%8,%9}, {%0,%1,%2,%3};"
        : "+f"(c[0]), "+f"(c[1]), "+f"(c[2]), "+f"(c[3])
        : "r"(a0), "r"(a1), "r"(a2), "r"(a3), "r"(b0), "r"(b1));
}

// ---------------------------------------------------------------------------
// Kernel 0: fp16 pre-pass.
//  blocks 0..255:   g_Ah = half([h_t | src])   (elementwise, float4 granular)
//  blocks 256..767: g_Bh[z][n][k] = half(Wa[z*512+k][n])  (32x32 tile transpose)
// ---------------------------------------------------------------------------
#define A4TOT (2 * TGT * BATCH * HID / 4)   // 524288 float4

__global__ __launch_bounds__(256) void prep_fp16(
    const float* __restrict__ h_t,
    const float* __restrict__ src,
    const float* __restrict__ Wa)
{
    const int bx  = blockIdx.x;
    const int tid = threadIdx.x;

    if (bx < 256) {
        for (int i = bx * 256 + tid; i < A4TOT; i += 256 * 256) {
            float4 v = (i < A4TOT / 2) ? ((const float4*)h_t)[i]
                                       : ((const float4*)src)[i - A4TOT / 2];
            __half2 lo = __float22half2_rn(make_float2(v.x, v.y));
            __half2 hi = __float22half2_rn(make_float2(v.z, v.w));
            uint2 pk;
            pk.x = *(uint32_t*)&lo;
            pk.y = *(uint32_t*)&hi;
            ((uint2*)g_Ah)[i] = pk;
        }
    } else {
        __shared__ float t[32][33];
        const int tile = bx - 256;            // 0..511
        const int z  = tile >> 8;
        const int rm = tile & 255;
        const int k0 = (rm & 15) * 32;
        const int n0 = (rm >> 4) * 32;
        const int tx = tid & 31, ty = tid >> 5;
#pragma unroll
        for (int r = 0; r < 32; r += 8)
            t[ty + r][tx] = Wa[(z * HID + k0 + ty + r) * ATT + n0 + tx];
        __syncthreads();
#pragma unroll
        for (int r = 0; r < 32; r += 8)
            g_Bh[z * HID * ATT + (n0 + ty + r) * HID + k0 + tx] =
                __float2half_rn(t[tx][ty + r]);
    }
}

// ---------------------------------------------------------------------------
// Kernel 1: fp16 mma GEMM, cp.async triple-buffered.
//   C[m][n] = sum_k Ah[z][m][k] * Bh[z][n][k]   (fp32 accum)
// CTA tile 128(M) x 64(N), K in 8 stages of 64. Grid (8 n, 32 m) = 256 CTAs,
// 2 CTAs/SM. Smem rows: 72 halves (36 words, 36%32=4 -> conflict-free frags).
// ---------------------------------------------------------------------------
#define KTH    64
#define RSH    72                         // halves per smem row
#define ASTGH  (128 * RSH)                // 9216 halves
#define BSTGH  (64 * RSH)                 // 4608 halves
#define STGH   (ASTGH + BSTGH)            // 13824 halves = 27648 B/stage

__global__ __launch_bounds__(256, 2) void gemm_mma_h(void)
{
    extern __shared__ __align__(16) __half smh[];
    const uint32_t smb = smem_u32(smh);

    const int tid  = threadIdx.x;
    const int lane = tid & 31;
    const int wid  = tid >> 5;
    const int g    = lane >> 2;
    const int tg   = lane & 3;

    const int wm = (wid >> 1) * 32;    // 0,32,64,96
    const int wn = (wid & 1) * 32;     // 0,32

    const int ntile = blockIdx.x;      // 0..7
    const int mtile = blockIdx.y;      // 0..31
    const int z  = mtile >> 4;
    const int m0 = (mtile & 15) * 128;
    const int n0 = ntile * 64;
    const __half* A = g_Ah + z * (TGT * BATCH * HID);
    const __half* B = g_Bh + z * (HID * ATT);
    float*        C = (z == 0) ? g_hpart : g_spart;

    auto stage = [&](int s, int bufi) {
        const int kt = s * KTH;
        const uint32_t bufA = smb + (uint32_t)(bufi * STGH) * 2u;
        const uint32_t bufB = bufA + (uint32_t)ASTGH * 2u;
        // A: 128 rows x 8 chunks (16B = 8 halves) = 1024 chunks, 4/thread
#pragma unroll
        for (int r = 0; r < 4; r++) {
            const int idx = r * 256 + tid;
            const int am = idx >> 3, ac = idx & 7;
            CP_ASYNC16(bufA + (uint32_t)(am * RSH + ac * 8) * 2u,
                       A + (m0 + am) * HID + kt + ac * 8);
        }
        // B: 64 rows x 8 chunks = 512 chunks, 2/thread
#pragma unroll
        for (int r = 0; r < 2; r++) {
            const int idx = r * 256 + tid;
            const int bn = idx >> 3, bc = idx & 7;
            CP_ASYNC16(bufB + (uint32_t)(bn * RSH + bc * 8) * 2u,
                       B + (n0 + bn) * HID + kt + bc * 8);
        }
    };

    float acc[2][4][4];
#pragma unroll
    for (int mi = 0; mi < 2; mi++)
#pragma unroll
        for (int ni = 0; ni < 4; ni++)
#pragma unroll
            for (int j = 0; j < 4; j++) acc[mi][ni][j] = 0.f;

    stage(0, 0); CP_COMMIT();
    stage(1, 1); CP_COMMIT();

    for (int s = 0; s < 8; s++) {
        if (s < 7) CP_WAIT1(); else CP_WAIT0();
        __syncthreads();
        if (s + 2 < 8) { stage(s + 2, (s + 2) % 3); CP_COMMIT(); }

        const __half* Ab = smh + (s % 3) * STGH;
        const __half* Bb = Ab + ASTGH;
#pragma unroll
        for (int ks = 0; ks < 4; ks++) {          // 4 k16-steps per stage
            const int k0 = ks * 16;
            uint32_t a[2][4];
#pragma unroll
            for (int mi = 0; mi < 2; mi++) {
                const __half* ap = Ab + (wm + mi * 16 + g) * RSH + k0 + 2 * tg;
                a[mi][0] = *(const uint32_t*)(ap);
                a[mi][1] = *(const uint32_t*)(ap + 8 * RSH);
                a[mi][2] = *(const uint32_t*)(ap + 8);
                a[mi][3] = *(const uint32_t*)(ap + 8 * RSH + 8);
            }
            uint32_t b[4][2];
#pragma unroll
            for (int ni = 0; ni < 4; ni++) {
                const __half* bp = Bb + (wn + ni * 8 + g) * RSH + k0 + 2 * tg;
                b[ni][0] = *(const uint32_t*)(bp);
                b[ni][1] = *(const uint32_t*)(bp + 8);
            }
#pragma unroll
            for (int mi = 0; mi < 2; mi++)
#pragma unroll
                for (int ni = 0; ni < 4; ni++)
                    mma_f16(acc[mi][ni], a[mi], b[ni]);
        }
    }

#pragma unroll
    for (int mi = 0; mi < 2; mi++) {
#pragma unroll
        for (int ni = 0; ni < 4; ni++) {
            const int row = m0 + wm + mi * 16 + g;
            const int col = n0 + wn + ni * 8 + 2 * tg;
            *(float2*)(C + row * ATT + col)       = make_float2(acc[mi][ni][0], acc[mi][ni][1]);
            *(float2*)(C + (row + 8) * ATT + col) = make_float2(acc[mi][ni][2], acc[mi][ni][3]);
        }
    }
}

// ---------------------------------------------------------------------------
// Kernel 2: fused scores + softmax. (unchanged from R11)
// ---------------------------------------------------------------------------
#define SSTR 516

__global__ __launch_bounds__(256) void scores_softmax_kernel(
    const float* __restrict__ Va)
{
    extern __shared__ float smem[];
    float* hs = smem;                 // 8  * SSTR
    float* ss = smem + 8 * SSTR;      // 16 * SSTR
    float* va = smem + 24 * SSTR;     // 512

    const int b   = blockIdx.y;
    const int t0  = blockIdx.x * 8;
    const int tid = threadIdx.x;

    const int ti   = tid >> 5;
    const int si   = tid & 31;
    const int sh   = si >> 4;
    const int sl   = si & 15;
    const int aoff = sh * 256;

    va[tid]       = Va[tid];
    va[tid + 256] = Va[tid + 256];

#pragma unroll
    for (int r = 0; r < 4; r++) {
        int idx  = r * 256 + tid;
        int row  = idx >> 7;
        int col4 = idx & 127;
        float4 v = *(const float4*)(g_hpart + ((t0 + row) * BATCH + b) * ATT + col4 * 4);
        *(float4*)(hs + row * SSTR + col4 * 4) = v;
    }

    float sc[4];

#pragma unroll
    for (int c = 0; c < 4; c++) {
        __syncthreads();
#pragma unroll
        for (int r = 0; r < 8; r++) {
            int idx  = r * 256 + tid;
            int row  = idx >> 7;
            int col4 = idx & 127;
            float4 v = *(const float4*)(g_spart + ((c * 16 + row) * BATCH + b) * ATT + col4 * 4);
            *(float4*)(ss + row * SSTR + col4 * 4) = v;
        }
        __syncthreads();

        const float* hp = hs + ti * SSTR + aoff;
        const float* sp = ss + sl * SSTR + aoff;
        const float* vp = va + aoff;
        float acc = 0.f;
#pragma unroll 4
        for (int a = 0; a < 256; a += 4) {
            float4 h4 = *(const float4*)(hp + a);
            float4 s4 = *(const float4*)(sp + a);
            float4 v4 = *(const float4*)(vp + a);
            acc = fmaf(tanh_fast(h4.x + s4.x), v4.x, acc);
            acc = fmaf(tanh_fast(h4.y + s4.y), v4.y, acc);
            acc = fmaf(tanh_fast(h4.z + s4.z), v4.z, acc);
            acc = fmaf(tanh_fast(h4.w + s4.w), v4.w, acc);
        }
        sc[c] = acc;
    }

#pragma unroll
    for (int c = 0; c < 4; c++)
        sc[c] += __shfl_xor_sync(0xffffffffu, sc[c], 16);

    float mx = fmaxf(fmaxf(sc[0], sc[1]), fmaxf(sc[2], sc[3]));
#pragma unroll
    for (int o = 1; o <= 8; o <<= 1)
        mx = fmaxf(mx, __shfl_xor_sync(0xffffffffu, mx, o));

    float e[4], sum = 0.f;
#pragma unroll
    for (int c = 0; c < 4; c++) { e[c] = __expf(sc[c] - mx); sum += e[c]; }
#pragma unroll
    for (int o = 1; o <= 8; o <<= 1)
        sum += __shfl_xor_sync(0xffffffffu, sum, o);

    const float inv = 1.0f / sum;
    if (sh == 0) {
        float* dst = g_scores + ((t0 + ti) * BATCH + b) * SRC;
#pragma unroll
        for (int c = 0; c < 4; c++)
            dst[c * 16 + sl] = to_tf32(e[c] * inv);
    }
}

// ---------------------------------------------------------------------------
// Kernel 3: lean tensor-core context. (unchanged from R11)
// ---------------------------------------------------------------------------
#define ASTR 68
#define CST2 68

__global__ __launch_bounds__(256) void context_kernel(
    const float* __restrict__ src,
    float* __restrict__ out)
{
    extern __shared__ float dsm[];
    float* at = dsm;
    float* ss = dsm + 64 * ASTR;

    const int b   = blockIdx.y;
    const int hc  = blockIdx.x;
    const int h0  = hc * 64;
    const int tid = threadIdx.x;
    const int wid  = tid >> 5;
    const int lane = tid & 31;

#pragma unroll
    for (int r = 0; r < 4; r++) {
        const int idx = r * 256 + tid;
        const int t   = idx >> 4;
        const int c4  = idx & 15;
        float4 v = *(const float4*)(g_scores + (t * BATCH + b) * SRC + c4 * 4);
        *(float4*)(at + t * ASTR + c4 * 4) = v;
    }
#pragma unroll
    for (int r = 0; r < 4; r++) {
        const int idx = r * 256 + tid;
        const int s   = idx >> 4;
        const int c4  = idx & 15;
        float4 v = *(const float4*)(src + (s * BATCH + b) * HID + h0 + c4 * 4);
        *(float4*)(ss + s * CST2 + c4 * 4) = to_tf32_4(v);
    }
    __syncthreads();

    const int g  = lane >> 2;
    const int tg = lane & 3;
    const int wm = (wid & 3) * 16;
    const int wn = (wid >> 2) * 32;

    float acc[4][4];
#pragma unroll
    for (int ni = 0; ni < 4; ni++)
#pragma unroll
        for (int j = 0; j < 4; j++) acc[ni][j] = 0.f;

#pragma unroll
    for (int ks = 0; ks < 8; ks++) {
        const int k0 = ks * 8;
        float a[4];
        {
            const float* ap = at + (wm + g) * ASTR + k0 + tg;
            a[0] = ap[0];
            a[1] = ap[8 * ASTR];
            a[2] = ap[4];
            a[3] = ap[8 * ASTR + 4];
        }
        float bfr[4][2];
#pragma unroll
        for (int ni = 0; ni < 4; ni++) {
            const float* bp = ss + (k0 + tg) * CST2 + wn + ni * 8 + g;
            bfr[ni][0] = bp[0];
            bfr[ni][1] = bp[4 * CST2];
        }
#pragma unroll
        for (int ni = 0; ni < 4; ni++)
            mma_tf32(acc[ni], a, bfr[ni]);
    }

#pragma unroll
    for (int ni = 0; ni < 4; ni++) {
        const int t   = wm + g;
        const int col = h0 + wn + ni * 8 + 2 * tg;
        *(float2*)(out + (t * BATCH + b) * HID + col)       = make_float2(acc[ni][0], acc[ni][1]);
        *(float2*)(out + ((t + 8) * BATCH + b) * HID + col) = make_float2(acc[ni][2], acc[ni][3]);
    }
}

// ---------------------------------------------------------------------------
extern "C" void kernel_launch(void* const* d_in, const int* in_sizes, int n_in,
                              void* d_out, int out_size)
{
    const float* h_t  = (const float*)d_in[0];   // (64, 32, 512)
    const float* srce = (const float*)d_in[1];   // (64, 32, 512)
    const float* Wa   = (const float*)d_in[2];   // (1024, 512)
    const float* Va   = (const float*)d_in[3];   // (512,)
    float* out = (float*)d_out;                  // (64, 32, 512)

    (void)in_sizes; (void)n_in; (void)out_size;

    // 0) fp16 pre-pass: A convert + W transpose
    prep_fp16<<<768, 256>>>(h_t, srce, Wa);

    // 1) fp16 GEMMs: grid (8 n, 32 m) = 256 CTAs, 2/SM
    const int gemm_smem = 3 * STGH * (int)sizeof(__half);   // 82944 B
    cudaFuncSetAttribute(gemm_mma_h,
                         cudaFuncAttributeMaxDynamicSharedMemorySize, gemm_smem);
    gemm_mma_h<<<dim3(8, 32), 256, gemm_smem>>>();

    // 2) fused scores + softmax: grid (8 t-tiles, 32 b) = 256 blocks
    const int sc_smem = (24 * SSTR + 512) * (int)sizeof(float);
    cudaFuncSetAttribute(scores_softmax_kernel,
                         cudaFuncAttributeMaxDynamicSharedMemorySize, sc_smem);
    scores_softmax_kernel<<<dim3(8, 32), 256, sc_smem>>>(Va);

    // 3) lean mma context: grid (8 hc, 32 b) = 256 blocks
    const int ctx_smem = (64 * ASTR + 64 * CST2) * (int)sizeof(float);
    cudaFuncSetAttribute(context_kernel,
                         cudaFuncAttributeMaxDynamicSharedMemorySize, ctx_smem);
    context_kernel<<<dim3(8, 32), 256, ctx_smem>>>(srce, out);
}

// round 14
// speedup vs baseline: 1.2827x; 1.0572x over previous
#include <cuda_runtime.h>
#include <cuda_bf16.h>
#include <cuda_fp16.h>
#include <math.h>
#include <cstdint>

// Problem dims
#define TGT   64
#define SRC   64
#define BATCH 32
#define HID   512
#define ATT   512

// Scratch (no cudaMalloc allowed)
__device__ float g_hpart[TGT * BATCH * ATT];   // [t*BATCH+b][a]
__device__ float g_spart[SRC * BATCH * ATT];   // [s*BATCH+b][a]
__device__ float g_scores[TGT * BATCH * SRC];  // normalized tf32 attn
__device__ __align__(16) __half g_Ah[2 * TGT * BATCH * HID]; // fp16 [h_t|src]
__device__ __align__(16) __half g_Bh[2 * HID * ATT];         // fp16 Wa^T: [z][n][k]

// ---------------------------------------------------------------------------
// helpers
// ---------------------------------------------------------------------------
__device__ __forceinline__ float to_tf32(float x) {
    uint32_t u;
    asm("cvt.rna.tf32.f32 %0, %1;" : "=r"(u) : "f"(x));
    return __uint_as_float(u);
}
__device__ __forceinline__ float4 to_tf32_4(float4 v) {
    return make_float4(to_tf32(v.x), to_tf32(v.y), to_tf32(v.z), to_tf32(v.w));
}
__device__ __forceinline__ float tanh_fast(float x) {
    float y;
    asm("tanh.approx.f32 %0, %1;" : "=f"(y) : "f"(x));
    return y;
}
__device__ __forceinline__ uint32_t smem_u32(const void* p) {
    uint32_t a;
    asm("{ .reg .u64 t; cvta.to.shared.u64 t, %1; cvt.u32.u64 %0, t; }"
        : "=r"(a) : "l"(p));
    return a;
}
#define CP_ASYNC16(dst, srcp) \
    asm volatile("cp.async.cg.shared.global [%0], [%1], 16;" :: "r"(dst), "l"(srcp))
#define CP_COMMIT() asm volatile("cp.async.commit_group;" ::: "memory")
#define CP_WAIT1()  asm volatile("cp.async.wait_group 1;" ::: "memory")
#define CP_WAIT0()  asm volatile("cp.async.wait_group 0;" ::: "memory")

#define LDSM_X4(r, addr)                                                       \
    asm volatile("ldmatrix.sync.aligned.m8n8.x4.shared.b16 {%0,%1,%2,%3}, [%4];" \
        : "=r"((r)[0]), "=r"((r)[1]), "=r"((r)[2]), "=r"((r)[3]) : "r"(addr))

// fp16 mma: D(f32) += A(f16) * B(f16), m16n8k16
__device__ __forceinline__ void mma_f16(float* c, const uint32_t* a, const uint32_t* b) {
    asm volatile(
        "mma.sync.aligned.m16n8k16.row.col.f32.f16.f16.f32 "
        "{%0,%1,%2,%3}, {%4,%5,%6,%7}, {%8,%9}, {%0,%1,%2,%3};"
        : "+f"(c[0]), "+f"(c[1]), "+f"(c[2]), "+f"(c[3])
        : "r"(a[0]), "r"(a[1]), "r"(a[2]), "r"(a[3]), "r"(b[0]), "r"(b[1]));
}

// tf32 mma (context kernel)
__device__ __forceinline__ void mma_tf32(float* c, const float* a, const float* b) {
    uint32_t a0 = __float_as_uint(a[0]), a1 = __float_as_uint(a[1]);
    uint32_t a2 = __float_as_uint(a[2]), a3 = __float_as_uint(a[3]);
    uint32_t b0 = __float_as_uint(b[0]), b1 = __float_as_uint(b[1]);
    asm volatile(
        "mma.sync.aligned.m16n8k8.row.col.f32.tf32.tf32.f32 "
        "{%0,%1,%2,%3}, {%4,%5,%6,%7}, {%8,%9}, {%0,%1,%2,%3};"
        : "+f"(c[0]), "+f"(c[1]), "+f"(c[2]), "+f"(c[3])
        : "r"(a0), "r"(a1), "r"(a2), "r"(a3), "r"(b0), "r"(b1));
}

// ---------------------------------------------------------------------------
// Kernel 0: fp16 pre-pass. (R12, unchanged)
// ---------------------------------------------------------------------------
#define A4TOT (2 * TGT * BATCH * HID / 4)   // 524288 float4

__global__ __launch_bounds__(256) void prep_fp16(
    const float* __restrict__ h_t,
    const float* __restrict__ src,
    const float* __restrict__ Wa)
{
    const int bx  = blockIdx.x;
    const int tid = threadIdx.x;

    if (bx < 256) {
        for (int i = bx * 256 + tid; i < A4TOT; i += 256 * 256) {
            float4 v = (i < A4TOT / 2) ? ((const float4*)h_t)[i]
                                       : ((const float4*)src)[i - A4TOT / 2];
            __half2 lo = __float22half2_rn(make_float2(v.x, v.y));
            __half2 hi = __float22half2_rn(make_float2(v.z, v.w));
            uint2 pk;
            pk.x = *(uint32_t*)&lo;
            pk.y = *(uint32_t*)&hi;
            ((uint2*)g_Ah)[i] = pk;
        }
    } else {
        __shared__ float t[32][33];
        const int tile = bx - 256;            // 0..511
        const int z  = tile >> 8;
        const int rm = tile & 255;
        const int k0 = (rm & 15) * 32;
        const int n0 = (rm >> 4) * 32;
        const int tx = tid & 31, ty = tid >> 5;
#pragma unroll
        for (int r = 0; r < 32; r += 8)
            t[ty + r][tx] = Wa[(z * HID + k0 + ty + r) * ATT + n0 + tx];
        __syncthreads();
#pragma unroll
        for (int r = 0; r < 32; r += 8)
            g_Bh[z * HID * ATT + (n0 + ty + r) * HID + k0 + tx] =
                __float2half_rn(t[tx][ty + r]);
    }
}

// ---------------------------------------------------------------------------
// Kernel 1: fp16 mma GEMM, cp.async triple-buffered, ldmatrix fragments.
// CTA tile 128(M) x 64(N), K in 8 stages of 64. 256 CTAs, 2 CTAs/SM.
// ---------------------------------------------------------------------------
#define KTH    64
#define RSH    72                         // halves per smem row (144B, 16B mult)
#define ASTGH  (128 * RSH)                // 9216 halves
#define BSTGH  (64 * RSH)                 // 4608 halves
#define STGH   (ASTGH + BSTGH)            // 13824 halves = 27648 B/stage

__global__ __launch_bounds__(256, 2) void gemm_mma_h(void)
{
    extern __shared__ __align__(16) __half smh[];
    const uint32_t smb = smem_u32(smh);

    const int tid  = threadIdx.x;
    const int lane = tid & 31;
    const int wid  = tid >> 5;
    const int g    = lane >> 2;
    const int tg   = lane & 3;

    const int wm = (wid >> 1) * 32;    // 0,32,64,96
    const int wn = (wid & 1) * 32;     // 0,32

    const int ntile = blockIdx.x;      // 0..7
    const int mtile = blockIdx.y;      // 0..31
    const int z  = mtile >> 4;
    const int m0 = (mtile & 15) * 128;
    const int n0 = ntile * 64;
    const __half* A = g_Ah + z * (TGT * BATCH * HID);
    const __half* B = g_Bh + z * (HID * ATT);
    float*        C = (z == 0) ? g_hpart : g_spart;

    // ldmatrix per-lane byte offsets within a stage buffer
    // A x4 (m16k16): row = wm + mi*16 + (lane&15), kcol = (lane>>4)*8
    const uint32_t aoff = (uint32_t)(((wm + (lane & 15)) * RSH + ((lane >> 4) << 3)) * 2);
    // B x4 (n16k16): row = wn + ((lane>>4)&1)*8 + (lane&7), kcol = ((lane>>3)&1)*8
    const uint32_t boff0 = (uint32_t)((ASTGH +
        (wn + (((lane >> 4) & 1) << 3) + (lane & 7)) * RSH + (((lane >> 3) & 1) << 3)) * 2);
    const uint32_t boff1 = boff0 + (uint32_t)(16 * RSH * 2);

    auto stage = [&](int s, int bufi) {
        const int kt = s * KTH;
        const uint32_t bufA = smb + (uint32_t)(bufi * STGH) * 2u;
        const uint32_t bufB = bufA + (uint32_t)ASTGH * 2u;
#pragma unroll
        for (int r = 0; r < 4; r++) {
            const int idx = r * 256 + tid;
            const int am = idx >> 3, ac = idx & 7;
            CP_ASYNC16(bufA + (uint32_t)(am * RSH + ac * 8) * 2u,
                       A + (m0 + am) * HID + kt + ac * 8);
        }
#pragma unroll
        for (int r = 0; r < 2; r++) {
            const int idx = r * 256 + tid;
            const int bn = idx >> 3, bc = idx & 7;
            CP_ASYNC16(bufB + (uint32_t)(bn * RSH + bc * 8) * 2u,
                       B + (n0 + bn) * HID + kt + bc * 8);
        }
    };

    float acc[2][4][4];
#pragma unroll
    for (int mi = 0; mi < 2; mi++)
#pragma unroll
        for (int ni = 0; ni < 4; ni++)
#pragma unroll
            for (int j = 0; j < 4; j++) acc[mi][ni][j] = 0.f;

    stage(0, 0); CP_COMMIT();
    stage(1, 1); CP_COMMIT();

    for (int s = 0; s < 8; s++) {
        if (s < 7) CP_WAIT1(); else CP_WAIT0();
        __syncthreads();
        if (s + 2 < 8) { stage(s + 2, (s + 2) % 3); CP_COMMIT(); }

        const uint32_t base = smb + (uint32_t)((s % 3) * STGH) * 2u;
#pragma unroll
        for (int ks = 0; ks < 4; ks++) {          // 4 k16-steps per stage
            const uint32_t koff = (uint32_t)(ks * 32);   // 16 halves
            uint32_t a[2][4], b2[2][4];
            LDSM_X4(a[0], base + aoff + koff);
            LDSM_X4(a[1], base + aoff + (uint32_t)(16 * RSH * 2) + koff);
            LDSM_X4(b2[0], base + boff0 + koff);
            LDSM_X4(b2[1], base + boff1 + koff);
#pragma unroll
            for (int mi = 0; mi < 2; mi++)
#pragma unroll
                for (int ni = 0; ni < 4; ni++)
                    mma_f16(acc[mi][ni], a[mi], &b2[ni >> 1][(ni & 1) * 2]);
        }
    }

#pragma unroll
    for (int mi = 0; mi < 2; mi++) {
#pragma unroll
        for (int ni = 0; ni < 4; ni++) {
            const int row = m0 + wm + mi * 16 + g;
            const int col = n0 + wn + ni * 8 + 2 * tg;
            *(float2*)(C + row * ATT + col)       = make_float2(acc[mi][ni][0], acc[mi][ni][1]);
            *(float2*)(C + (row + 8) * ATT + col) = make_float2(acc[mi][ni][2], acc[mi][ni][3]);
        }
    }
}

// ---------------------------------------------------------------------------
// Kernel 2: fused scores + softmax. (R12, unchanged — passing)
// ---------------------------------------------------------------------------
#define SSTR 516

__global__ __launch_bounds__(256) void scores_softmax_kernel(
    const float* __restrict__ Va)
{
    extern __shared__ float smem[];
    float* hs = smem;                 // 8  * SSTR
    float* ss = smem + 8 * SSTR;      // 16 * SSTR
    float* va = smem + 24 * SSTR;     // 512

    const int b   = blockIdx.y;
    const int t0  = blockIdx.x * 8;
    const int tid = threadIdx.x;

    const int ti   = tid >> 5;
    const int si   = tid & 31;
    const int sh   = si >> 4;
    const int sl   = si & 15;
    const int aoff = sh * 256;

    va[tid]       = Va[tid];
    va[tid + 256] = Va[tid + 256];

#pragma unroll
    for (int r = 0; r < 4; r++) {
        int idx  = r * 256 + tid;
        int row  = idx >> 7;
        int col4 = idx & 127;
        float4 v = *(const float4*)(g_hpart + ((t0 + row) * BATCH + b) * ATT + col4 * 4);
        *(float4*)(hs + row * SSTR + col4 * 4) = v;
    }

    float sc[4];

#pragma unroll
    for (int c = 0; c < 4; c++) {
        __syncthreads();
#pragma unroll
        for (int r = 0; r < 8; r++) {
            int idx  = r * 256 + tid;
            int row  = idx >> 7;
            int col4 = idx & 127;
            float4 v = *(const float4*)(g_spart + ((c * 16 + row) * BATCH + b) * ATT + col4 * 4);
            *(float4*)(ss + row * SSTR + col4 * 4) = v;
        }
        __syncthreads();

        const float* hp = hs + ti * SSTR + aoff;
        const float* sp = ss + sl * SSTR + aoff;
        const float* vp = va + aoff;
        float acc = 0.f;
#pragma unroll 4
        for (int a = 0; a < 256; a += 4) {
            float4 h4 = *(const float4*)(hp + a);
            float4 s4 = *(const float4*)(sp + a);
            float4 v4 = *(const float4*)(vp + a);
            acc = fmaf(tanh_fast(h4.x + s4.x), v4.x, acc);
            acc = fmaf(tanh_fast(h4.y + s4.y), v4.y, acc);
            acc = fmaf(tanh_fast(h4.z + s4.z), v4.z, acc);
            acc = fmaf(tanh_fast(h4.w + s4.w), v4.w, acc);
        }
        sc[c] = acc;
    }

#pragma unroll
    for (int c = 0; c < 4; c++)
        sc[c] += __shfl_xor_sync(0xffffffffu, sc[c], 16);

    float mx = fmaxf(fmaxf(sc[0], sc[1]), fmaxf(sc[2], sc[3]));
#pragma unroll
    for (int o = 1; o <= 8; o <<= 1)
        mx = fmaxf(mx, __shfl_xor_sync(0xffffffffu, mx, o));

    float e[4], sum = 0.f;
#pragma unroll
    for (int c = 0; c < 4; c++) { e[c] = __expf(sc[c] - mx); sum += e[c]; }
#pragma unroll
    for (int o = 1; o <= 8; o <<= 1)
        sum += __shfl_xor_sync(0xffffffffu, sum, o);

    const float inv = 1.0f / sum;
    if (sh == 0) {
        float* dst = g_scores + ((t0 + ti) * BATCH + b) * SRC;
#pragma unroll
        for (int c = 0; c < 4; c++)
            dst[c * 16 + sl] = to_tf32(e[c] * inv);
    }
}

// ---------------------------------------------------------------------------
// Kernel 3: lean tensor-core context. (R12, unchanged — passing)
// ---------------------------------------------------------------------------
#define ASTR 68
#define CST2 68

__global__ __launch_bounds__(256) void context_kernel(
    const float* __restrict__ src,
    float* __restrict__ out)
{
    extern __shared__ float dsm[];
    float* at = dsm;
    float* ss = dsm + 64 * ASTR;

    const int b   = blockIdx.y;
    const int hc  = blockIdx.x;
    const int h0  = hc * 64;
    const int tid = threadIdx.x;
    const int wid  = tid >> 5;
    const int lane = tid & 31;

#pragma unroll
    for (int r = 0; r < 4; r++) {
        const int idx = r * 256 + tid;
        const int t   = idx >> 4;
        const int c4  = idx & 15;
        float4 v = *(const float4*)(g_scores + (t * BATCH + b) * SRC + c4 * 4);
        *(float4*)(at + t * ASTR + c4 * 4) = v;
    }
#pragma unroll
    for (int r = 0; r < 4; r++) {
        const int idx = r * 256 + tid;
        const int s   = idx >> 4;
        const int c4  = idx & 15;
        float4 v = *(const float4*)(src + (s * BATCH + b) * HID + h0 + c4 * 4);
        *(float4*)(ss + s * CST2 + c4 * 4) = to_tf32_4(v);
    }
    __syncthreads();

    const int g  = lane >> 2;
    const int tg = lane & 3;
    const int wm = (wid & 3) * 16;
    const int wn = (wid >> 2) * 32;

    float acc[4][4];
#pragma unroll
    for (int ni = 0; ni < 4; ni++)
#pragma unroll
        for (int j = 0; j < 4; j++) acc[ni][j] = 0.f;

#pragma unroll
    for (int ks = 0; ks < 8; ks++) {
        const int k0 = ks * 8;
        float a[4];
        {
            const float* ap = at + (wm + g) * ASTR + k0 + tg;
            a[0] = ap[0];
            a[1] = ap[8 * ASTR];
            a[2] = ap[4];
            a[3] = ap[8 * ASTR + 4];
        }
        float bfr[4][2];
#pragma unroll
        for (int ni = 0; ni < 4; ni++) {
            const float* bp = ss + (k0 + tg) * CST2 + wn + ni * 8 + g;
            bfr[ni][0] = bp[0];
            bfr[ni][1] = bp[4 * CST2];
        }
#pragma unroll
        for (int ni = 0; ni < 4; ni++)
            mma_tf32(acc[ni], a, bfr[ni]);
    }

#pragma unroll
    for (int ni = 0; ni < 4; ni++) {
        const int t   = wm + g;
        const int col = h0 + wn + ni * 8 + 2 * tg;
        *(float2*)(out + (t * BATCH + b) * HID + col)       = make_float2(acc[ni][0], acc[ni][1]);
        *(float2*)(out + ((t + 8) * BATCH + b) * HID + col) = make_float2(acc[ni][2], acc[ni][3]);
    }
}

// ---------------------------------------------------------------------------
extern "C" void kernel_launch(void* const* d_in, const int* in_sizes, int n_in,
                              void* d_out, int out_size)
{
    const float* h_t  = (const float*)d_in[0];   // (64, 32, 512)
    const float* srce = (const float*)d_in[1];   // (64, 32, 512)
    const float* Wa   = (const float*)d_in[2];   // (1024, 512)
    const float* Va   = (const float*)d_in[3];   // (512,)
    float* out = (float*)d_out;                  // (64, 32, 512)

    (void)in_sizes; (void)n_in; (void)out_size;

    // 0) fp16 pre-pass: A convert + W transpose
    prep_fp16<<<768, 256>>>(h_t, srce, Wa);

    // 1) fp16 GEMMs (ldmatrix fragments): grid (8 n, 32 m) = 256 CTAs, 2/SM
    const int gemm_smem = 3 * STGH * (int)sizeof(__half);   // 82944 B
    cudaFuncSetAttribute(gemm_mma_h,
                         cudaFuncAttributeMaxDynamicSharedMemorySize, gemm_smem);
    gemm_mma_h<<<dim3(8, 32), 256, gemm_smem>>>();

    // 2) fused scores + softmax: grid (8 t-tiles, 32 b) = 256 blocks
    const int sc_smem = (24 * SSTR + 512) * (int)sizeof(float);
    cudaFuncSetAttribute(scores_softmax_kernel,
                         cudaFuncAttributeMaxDynamicSharedMemorySize, sc_smem);
    scores_softmax_kernel<<<dim3(8, 32), 256, sc_smem>>>(Va);

    // 3) lean mma context: grid (8 hc, 32 b) = 256 blocks
    const int ctx_smem = (64 * ASTR + 64 * CST2) * (int)sizeof(float);
    cudaFuncSetAttribute(context_kernel,
                         cudaFuncAttributeMaxDynamicSharedMemorySize, ctx_smem);
    context_kernel<<<dim3(8, 32), 256, ctx_smem>>>(srce, out);
}

// round 15
// speedup vs baseline: 1.3287x; 1.0359x over previous
#include <cuda_runtime.h>
#include <cuda_bf16.h>
#include <cuda_fp16.h>
#include <math.h>
#include <cstdint>

// Problem dims
#define TGT   64
#define SRC   64
#define BATCH 32
#define HID   512
#define ATT   512

// Scratch (no cudaMalloc allowed)
__device__ float g_hpart[TGT * BATCH * ATT];   // [t*BATCH+b][a]
__device__ float g_spart[SRC * BATCH * ATT];   // [s*BATCH+b][a]
__device__ __align__(16) __half g_attn[TGT * BATCH * SRC];   // fp16 attn [t][b][s]
__device__ __align__(16) __half g_Ah[2 * TGT * BATCH * HID]; // fp16 [h_t|src]
__device__ __align__(16) __half g_Bh[2 * HID * ATT];         // fp16 Wa^T: [z][n][k]
__device__ __align__(16) __half g_SrcT[BATCH * HID * SRC];   // fp16 src^T: [b][h][s]

// ---------------------------------------------------------------------------
// helpers
// ---------------------------------------------------------------------------
__device__ __forceinline__ float tanh_fast(float x) {
    float y;
    asm("tanh.approx.f32 %0, %1;" : "=f"(y) : "f"(x));
    return y;
}
__device__ __forceinline__ uint32_t smem_u32(const void* p) {
    uint32_t a;
    asm("{ .reg .u64 t; cvta.to.shared.u64 t, %1; cvt.u32.u64 %0, t; }"
        : "=r"(a) : "l"(p));
    return a;
}
#define CP_ASYNC16(dst, srcp) \
    asm volatile("cp.async.cg.shared.global [%0], [%1], 16;" :: "r"(dst), "l"(srcp))
#define CP_COMMIT() asm volatile("cp.async.commit_group;" ::: "memory")
#define CP_WAIT1()  asm volatile("cp.async.wait_group 1;" ::: "memory")
#define CP_WAIT0()  asm volatile("cp.async.wait_group 0;" ::: "memory")

#define LDSM_X4(r, addr)                                                       \
    asm volatile("ldmatrix.sync.aligned.m8n8.x4.shared.b16 {%0,%1,%2,%3}, [%4];" \
        : "=r"((r)[0]), "=r"((r)[1]), "=r"((r)[2]), "=r"((r)[3]) : "r"(addr))

// fp16 mma: D(f32) += A(f16) * B(f16), m16n8k16
__device__ __forceinline__ void mma_f16(float* c, const uint32_t* a, const uint32_t* b) {
    asm volatile(
        "mma.sync.aligned.m16n8k16.row.col.f32.f16.f16.f32 "
        "{%0,%1,%2,%3}, {%4,%5,%6,%7}, {%8,%9}, {%0,%1,%2,%3};"
        : "+f"(c[0]), "+f"(c[1]), "+f"(c[2]), "+f"(c[3])
        : "r"(a[0]), "r"(a[1]), "r"(a[2]), "r"(a[3]), "r"(b[0]), "r"(b[1]));
}

// ---------------------------------------------------------------------------
// Kernel 0: fp16 pre-pass.
//  bx 0..255:    g_Ah = half([h_t | src])
//  bx 256..767:  g_Bh[z][n][k] = half(Wa[z*512+k][n])    (32x32 transposes)
//  bx 768..1791: g_SrcT[b][h][s] = half(src[s][b][h])    (32x32 transposes)
// ---------------------------------------------------------------------------
#define A4TOT (2 * TGT * BATCH * HID / 4)   // 524288 float4

__global__ __launch_bounds__(256) void prep_fp16(
    const float* __restrict__ h_t,
    const float* __restrict__ src,
    const float* __restrict__ Wa)
{
    const int bx  = blockIdx.x;
    const int tid = threadIdx.x;

    if (bx < 256) {
        for (int i = bx * 256 + tid; i < A4TOT; i += 256 * 256) {
            float4 v = (i < A4TOT / 2) ? ((const float4*)h_t)[i]
                                       : ((const float4*)src)[i - A4TOT / 2];
            __half2 lo = __float22half2_rn(make_float2(v.x, v.y));
            __half2 hi = __float22half2_rn(make_float2(v.z, v.w));
            uint2 pk;
            pk.x = *(uint32_t*)&lo;
            pk.y = *(uint32_t*)&hi;
            ((uint2*)g_Ah)[i] = pk;
        }
    } else if (bx < 768) {
        __shared__ float t[32][33];
        const int tile = bx - 256;            // 0..511
        const int z  = tile >> 8;
        const int rm = tile & 255;
        const int k0 = (rm & 15) * 32;
        const int n0 = (rm >> 4) * 32;
        const int tx = tid & 31, ty = tid >> 5;
#pragma unroll
        for (int r = 0; r < 32; r += 8)
            t[ty + r][tx] = Wa[(z * HID + k0 + ty + r) * ATT + n0 + tx];
        __syncthreads();
#pragma unroll
        for (int r = 0; r < 32; r += 8)
            g_Bh[z * HID * ATT + (n0 + ty + r) * HID + k0 + tx] =
                __float2half_rn(t[tx][ty + r]);
    } else {
        __shared__ float t[32][33];
        const int tile = bx - 768;            // 0..1023
        const int b  = tile >> 5;             // 0..31
        const int rm = tile & 31;
        const int s0 = (rm & 1) * 32;         // 0,32
        const int h0 = (rm >> 1) * 32;        // 0..480
        const int tx = tid & 31, ty = tid >> 5;
#pragma unroll
        for (int r = 0; r < 32; r += 8)
            t[ty + r][tx] = src[((s0 + ty + r) * BATCH + b) * HID + h0 + tx];
        __syncthreads();
#pragma unroll
        for (int r = 0; r < 32; r += 8)
            g_SrcT[(b * HID + h0 + ty + r) * SRC + s0 + tx] =
                __float2half_rn(t[tx][ty + r]);
    }
}

// ---------------------------------------------------------------------------
// Kernel 1: fp16 mma GEMM, cp.async triple-buffered, ldmatrix fragments.
// (R14, unchanged — passing)
// ---------------------------------------------------------------------------
#define KTH    64
#define RSH    72
#define ASTGH  (128 * RSH)
#define BSTGH  (64 * RSH)
#define STGH   (ASTGH + BSTGH)

__global__ __launch_bounds__(256, 2) void gemm_mma_h(void)
{
    extern __shared__ __align__(16) __half smh[];
    const uint32_t smb = smem_u32(smh);

    const int tid  = threadIdx.x;
    const int lane = tid & 31;
    const int wid  = tid >> 5;
    const int g    = lane >> 2;
    const int tg   = lane & 3;

    const int wm = (wid >> 1) * 32;
    const int wn = (wid & 1) * 32;

    const int ntile = blockIdx.x;
    const int mtile = blockIdx.y;
    const int z  = mtile >> 4;
    const int m0 = (mtile & 15) * 128;
    const int n0 = ntile * 64;
    const __half* A = g_Ah + z * (TGT * BATCH * HID);
    const __half* B = g_Bh + z * (HID * ATT);
    float*        C = (z == 0) ? g_hpart : g_spart;

    const uint32_t aoff = (uint32_t)(((wm + (lane & 15)) * RSH + ((lane >> 4) << 3)) * 2);
    const uint32_t boff0 = (uint32_t)((ASTGH +
        (wn + (((lane >> 4) & 1) << 3) + (lane & 7)) * RSH + (((lane >> 3) & 1) << 3)) * 2);
    const uint32_t boff1 = boff0 + (uint32_t)(16 * RSH * 2);

    auto stage = [&](int s, int bufi) {
        const int kt = s * KTH;
        const uint32_t bufA = smb + (uint32_t)(bufi * STGH) * 2u;
        const uint32_t bufB = bufA + (uint32_t)ASTGH * 2u;
#pragma unroll
        for (int r = 0; r < 4; r++) {
            const int idx = r * 256 + tid;
            const int am = idx >> 3, ac = idx & 7;
            CP_ASYNC16(bufA + (uint32_t)(am * RSH + ac * 8) * 2u,
                       A + (m0 + am) * HID + kt + ac * 8);
        }
#pragma unroll
        for (int r = 0; r < 2; r++) {
            const int idx = r * 256 + tid;
            const int bn = idx >> 3, bc = idx & 7;
            CP_ASYNC16(bufB + (uint32_t)(bn * RSH + bc * 8) * 2u,
                       B + (n0 + bn) * HID + kt + bc * 8);
        }
    };

    float acc[2][4][4];
#pragma unroll
    for (int mi = 0; mi < 2; mi++)
#pragma unroll
        for (int ni = 0; ni < 4; ni++)
#pragma unroll
            for (int j = 0; j < 4; j++) acc[mi][ni][j] = 0.f;

    stage(0, 0); CP_COMMIT();
    stage(1, 1); CP_COMMIT();

    for (int s = 0; s < 8; s++) {
        if (s < 7) CP_WAIT1(); else CP_WAIT0();
        __syncthreads();
        if (s + 2 < 8) { stage(s + 2, (s + 2) % 3); CP_COMMIT(); }

        const uint32_t base = smb + (uint32_t)((s % 3) * STGH) * 2u;
#pragma unroll
        for (int ks = 0; ks < 4; ks++) {
            const uint32_t koff = (uint32_t)(ks * 32);
            uint32_t a[2][4], b2[2][4];
            LDSM_X4(a[0], base + aoff + koff);
            LDSM_X4(a[1], base + aoff + (uint32_t)(16 * RSH * 2) + koff);
            LDSM_X4(b2[0], base + boff0 + koff);
            LDSM_X4(b2[1], base + boff1 + koff);
#pragma unroll
            for (int mi = 0; mi < 2; mi++)
#pragma unroll
                for (int ni = 0; ni < 4; ni++)
                    mma_f16(acc[mi][ni], a[mi], &b2[ni >> 1][(ni & 1) * 2]);
        }
    }

#pragma unroll
    for (int mi = 0; mi < 2; mi++) {
#pragma unroll
        for (int ni = 0; ni < 4; ni++) {
            const int row = m0 + wm + mi * 16 + g;
            const int col = n0 + wn + ni * 8 + 2 * tg;
            *(float2*)(C + row * ATT + col)       = make_float2(acc[mi][ni][0], acc[mi][ni][1]);
            *(float2*)(C + (row + 8) * ATT + col) = make_float2(acc[mi][ni][2], acc[mi][ni][3]);
        }
    }
}

// ---------------------------------------------------------------------------
// Kernel 2: fused scores + softmax -> fp16 attn. (R12 scheme; fp16 output)
// ---------------------------------------------------------------------------
#define SSTR 516

__global__ __launch_bounds__(256) void scores_softmax_kernel(
    const float* __restrict__ Va)
{
    extern __shared__ float smem[];
    float* hs = smem;                 // 8  * SSTR
    float* ss = smem + 8 * SSTR;      // 16 * SSTR
    float* va = smem + 24 * SSTR;     // 512

    const int b   = blockIdx.y;
    const int t0  = blockIdx.x * 8;
    const int tid = threadIdx.x;

    const int ti   = tid >> 5;
    const int si   = tid & 31;
    const int sh   = si >> 4;
    const int sl   = si & 15;
    const int aoff = sh * 256;

    va[tid]       = Va[tid];
    va[tid + 256] = Va[tid + 256];

#pragma unroll
    for (int r = 0; r < 4; r++) {
        int idx  = r * 256 + tid;
        int row  = idx >> 7;
        int col4 = idx & 127;
        float4 v = *(const float4*)(g_hpart + ((t0 + row) * BATCH + b) * ATT + col4 * 4);
        *(float4*)(hs + row * SSTR + col4 * 4) = v;
    }

    float sc[4];

#pragma unroll
    for (int c = 0; c < 4; c++) {
        __syncthreads();
#pragma unroll
        for (int r = 0; r < 8; r++) {
            int idx  = r * 256 + tid;
            int row  = idx >> 7;
            int col4 = idx & 127;
            float4 v = *(const float4*)(g_spart + ((c * 16 + row) * BATCH + b) * ATT + col4 * 4);
            *(float4*)(ss + row * SSTR + col4 * 4) = v;
        }
        __syncthreads();

        const float* hp = hs + ti * SSTR + aoff;
        const float* sp = ss + sl * SSTR + aoff;
        const float* vp = va + aoff;
        float acc = 0.f;
#pragma unroll 4
        for (int a = 0; a < 256; a += 4) {
            float4 h4 = *(const float4*)(hp + a);
            float4 s4 = *(const float4*)(sp + a);
            float4 v4 = *(const float4*)(vp + a);
            acc = fmaf(tanh_fast(h4.x + s4.x), v4.x, acc);
            acc = fmaf(tanh_fast(h4.y + s4.y), v4.y, acc);
            acc = fmaf(tanh_fast(h4.z + s4.z), v4.z, acc);
            acc = fmaf(tanh_fast(h4.w + s4.w), v4.w, acc);
        }
        sc[c] = acc;
    }

#pragma unroll
    for (int c = 0; c < 4; c++)
        sc[c] += __shfl_xor_sync(0xffffffffu, sc[c], 16);

    float mx = fmaxf(fmaxf(sc[0], sc[1]), fmaxf(sc[2], sc[3]));
#pragma unroll
    for (int o = 1; o <= 8; o <<= 1)
        mx = fmaxf(mx, __shfl_xor_sync(0xffffffffu, mx, o));

    float e[4], sum = 0.f;
#pragma unroll
    for (int c = 0; c < 4; c++) { e[c] = __expf(sc[c] - mx); sum += e[c]; }
#pragma unroll
    for (int o = 1; o <= 8; o <<= 1)
        sum += __shfl_xor_sync(0xffffffffu, sum, o);

    const float inv = 1.0f / sum;
    if (sh == 0) {
        __half* dst = g_attn + ((t0 + ti) * BATCH + b) * SRC;
#pragma unroll
        for (int c = 0; c < 4; c++)
            dst[c * 16 + sl] = __float2half_rn(e[c] * inv);
    }
}

// ---------------------------------------------------------------------------
// Kernel 3: fp16 tensor-core context, non-trans ldmatrix only.
//   out[t][b][h] = sum_s attn[t][s] * srcT[h][s]
// Block: 128 threads, (hc of 64 h) x (t-half of 32 t) x b. Grid 512 blocks.
// mma M=32(t) x N=64(h') x K=64(s); warp wid owns n-slice wid*16.
// ---------------------------------------------------------------------------
#define CTH 72   // smem stride (halves), same conflict-free geometry as gemm

__global__ __launch_bounds__(128) void context_kernel(
    float* __restrict__ out)
{
    extern __shared__ __align__(16) __half csm[];
    const uint32_t atb = smem_u32(csm);                 // attn: 32 * CTH halves
    const uint32_t stb = atb + (uint32_t)(32 * CTH) * 2u; // srcT: 64 * CTH halves

    const int hc  = blockIdx.x;      // 0..7
    const int th  = blockIdx.y;      // 0..1
    const int b   = blockIdx.z;      // 0..31
    const int h0  = hc * 64;
    const int tt0 = th * 32;
    const int tid = threadIdx.x;
    const int lane = tid & 31;
    const int wid  = tid >> 5;       // 0..3

    // stage attn tile [32 t][64 s]: 256 16B-chunks, 2/thread
#pragma unroll
    for (int r = 0; r < 2; r++) {
        const int idx = r * 128 + tid;
        const int row = idx >> 3, c = idx & 7;
        CP_ASYNC16(atb + (uint32_t)(row * CTH + c * 8) * 2u,
                   g_attn + ((tt0 + row) * BATCH + b) * SRC + c * 8);
    }
    // stage srcT tile [64 h][64 s]: 512 chunks, 4/thread
#pragma unroll
    for (int r = 0; r < 4; r++) {
        const int idx = r * 128 + tid;
        const int row = idx >> 3, c = idx & 7;
        CP_ASYNC16(stb + (uint32_t)(row * CTH + c * 8) * 2u,
                   g_SrcT + (b * HID + h0 + row) * SRC + c * 8);
    }
    CP_COMMIT(); CP_WAIT0();
    __syncthreads();

    // fragment lane offsets (identical formulas to the passing gemm)
    const uint32_t aoff = atb + (uint32_t)(((lane & 15) * CTH + ((lane >> 4) << 3)) * 2);
    const uint32_t boff = stb + (uint32_t)(((wid * 16 + (((lane >> 4) & 1) << 3) + (lane & 7)) * CTH
                                            + (((lane >> 3) & 1) << 3)) * 2);

    float acc[2][2][4];
#pragma unroll
    for (int mi = 0; mi < 2; mi++)
#pragma unroll
        for (int ni = 0; ni < 2; ni++)
#pragma unroll
            for (int j = 0; j < 4; j++) acc[mi][ni][j] = 0.f;

#pragma unroll
    for (int ks = 0; ks < 4; ks++) {
        const uint32_t koff = (uint32_t)(ks * 32);    // 16 halves
        uint32_t a[2][4], b4[4];
        LDSM_X4(a[0], aoff + koff);
        LDSM_X4(a[1], aoff + (uint32_t)(16 * CTH * 2) + koff);
        LDSM_X4(b4, boff + koff);
#pragma unroll
        for (int mi = 0; mi < 2; mi++)
#pragma unroll
            for (int ni = 0; ni < 2; ni++)
                mma_f16(acc[mi][ni], a[mi], &b4[ni * 2]);
    }

    const int g  = lane >> 2;
    const int tg = lane & 3;
#pragma unroll
    for (int mi = 0; mi < 2; mi++) {
#pragma unroll
        for (int ni = 0; ni < 2; ni++) {
            const int t   = tt0 + mi * 16 + g;
            const int col = h0 + wid * 16 + ni * 8 + 2 * tg;
            *(float2*)(out + (t * BATCH + b) * HID + col)       = make_float2(acc[mi][ni][0], acc[mi][ni][1]);
            *(float2*)(out + ((t + 8) * BATCH + b) * HID + col) = make_float2(acc[mi][ni][2], acc[mi][ni][3]);
        }
    }
}

// ---------------------------------------------------------------------------
extern "C" void kernel_launch(void* const* d_in, const int* in_sizes, int n_in,
                              void* d_out, int out_size)
{
    const float* h_t  = (const float*)d_in[0];   // (64, 32, 512)
    const float* srce = (const float*)d_in[1];   // (64, 32, 512)
    const float* Wa   = (const float*)d_in[2];   // (1024, 512)
    const float* Va   = (const float*)d_in[3];   // (512,)
    float* out = (float*)d_out;                  // (64, 32, 512)

    (void)in_sizes; (void)n_in; (void)out_size;

    // 0) fp16 pre-pass: A convert + W transpose + src transpose
    prep_fp16<<<1792, 256>>>(h_t, srce, Wa);

    // 1) fp16 GEMMs (ldmatrix): grid (8 n, 32 m) = 256 CTAs, 2/SM
    const int gemm_smem = 3 * STGH * (int)sizeof(__half);   // 82944 B
    cudaFuncSetAttribute(gemm_mma_h,
                         cudaFuncAttributeMaxDynamicSharedMemorySize, gemm_smem);
    gemm_mma_h<<<dim3(8, 32), 256, gemm_smem>>>();

    // 2) fused scores + softmax: grid (8 t-tiles, 32 b) = 256 blocks
    const int sc_smem = (24 * SSTR + 512) * (int)sizeof(float);
    cudaFuncSetAttribute(scores_softmax_kernel,
                         cudaFuncAttributeMaxDynamicSharedMemorySize, sc_smem);
    scores_softmax_kernel<<<dim3(8, 32), 256, sc_smem>>>(Va);

    // 3) fp16 mma context: grid (8 hc, 2 th, 32 b) = 512 blocks, 128 thr
    const int ctx_smem = (32 + 64) * CTH * (int)sizeof(__half);   // 13824 B
    cudaFuncSetAttribute(context_kernel,
                         cudaFuncAttributeMaxDynamicSharedMemorySize, ctx_smem);
    context_kernel<<<dim3(8, 2, 32), 128, ctx_smem>>>(out);
}